// round 6
// baseline (speedup 1.0000x reference)
#include <cuda_runtime.h>
#include <cuda_bf16.h>
#include <cstdint>
#include <cstddef>

// Problem constants
#define B_  4
#define T_  2048
#define C_  1024
#define H_  16
#define D_  64
#define M_TOK (B_ * T_)      // 8192
#define C3 (3 * C_)          // 3072
#define GK 1024              // K of both GEMMs

// ---------------------------------------------------------------------------
// Scratch (device globals; allocation in kernel_launch is forbidden)
// ---------------------------------------------------------------------------
__device__ float g_qkv[(size_t)M_TOK * C3];  // [B*T, 3C] fp32
__device__ __nv_bfloat16 g_xhi[(size_t)M_TOK * C_];
__device__ __nv_bfloat16 g_xlo[(size_t)M_TOK * C_];
__device__ __nv_bfloat16 g_yhi[(size_t)M_TOK * C_];
__device__ __nv_bfloat16 g_ylo[(size_t)M_TOK * C_];
__device__ __nv_bfloat16 g_wahi[(size_t)C3 * C_];  // W_attn^T [3C][C]
__device__ __nv_bfloat16 g_walo[(size_t)C3 * C_];
__device__ __nv_bfloat16 g_wphi[(size_t)C_ * C_];  // W_proj^T [C][C]
__device__ __nv_bfloat16 g_wplo[(size_t)C_ * C_];

// ---------------------------------------------------------------------------
// PTX helpers (base sm_100-legal: mma.sync / ldmatrix / cp.async only)
// ---------------------------------------------------------------------------
__device__ __forceinline__ uint32_t smem_u32(const void* p) {
    uint32_t a;
    asm("{ .reg .u64 t; cvta.to.shared.u64 t, %1; cvt.u32.u64 %0, t; }"
        : "=r"(a) : "l"(p));
    return a;
}
__device__ __forceinline__ void cp_async16(uint32_t dst, const void* src) {
    asm volatile("cp.async.cg.shared.global [%0], [%1], 16;"
                 :: "r"(dst), "l"(src) : "memory");
}
__device__ __forceinline__ void cp_commit() {
    asm volatile("cp.async.commit_group;" ::: "memory");
}
template <int N>
__device__ __forceinline__ void cp_wait() {
    asm volatile("cp.async.wait_group %0;" :: "n"(N) : "memory");
}
__device__ __forceinline__ void ldm_x4(uint32_t* r, uint32_t addr) {
    asm volatile("ldmatrix.sync.aligned.m8n8.x4.shared.b16 {%0,%1,%2,%3}, [%4];"
                 : "=r"(r[0]), "=r"(r[1]), "=r"(r[2]), "=r"(r[3]) : "r"(addr));
}
// NOTE: non-volatile — pure register compute; lets ptxas schedule/interleave
// MMAs to hide tensor-pipe RAW latency.
__device__ __forceinline__ void mma_bf16(float* d, const uint32_t* a,
                                         uint32_t b0, uint32_t b1) {
    asm("mma.sync.aligned.m16n8k16.row.col.f32.bf16.bf16.f32 "
        "{%0,%1,%2,%3}, {%4,%5,%6,%7}, {%8,%9}, {%0,%1,%2,%3};"
        : "+f"(d[0]), "+f"(d[1]), "+f"(d[2]), "+f"(d[3])
        : "r"(a[0]), "r"(a[1]), "r"(a[2]), "r"(a[3]), "r"(b0), "r"(b1));
}
__device__ __forceinline__ uint32_t b2u(__nv_bfloat162 v) {
    return *reinterpret_cast<uint32_t*>(&v);
}
// split a float pair into bf16x2 hi + bf16x2 residual
__device__ __forceinline__ void split_pair(float x, float y,
                                           uint32_t& hi, uint32_t& lo) {
    __nv_bfloat162 h = __float22bfloat162_rn(make_float2(x, y));
    float2 hf = __bfloat1622float2(h);
    __nv_bfloat162 l = __float22bfloat162_rn(make_float2(x - hf.x, y - hf.y));
    hi = b2u(h); lo = b2u(l);
}

// ---------------------------------------------------------------------------
// Conversion kernels
// ---------------------------------------------------------------------------
__global__ void split_kernel(const float* __restrict__ in,
                             __nv_bfloat16* __restrict__ hi,
                             __nv_bfloat16* __restrict__ lo, int n)
{
    int i = (blockIdx.x * blockDim.x + threadIdx.x) * 8;
    if (i >= n) return;
    float4 a = *(const float4*)(in + i);
    float4 b = *(const float4*)(in + i + 4);
    float v[8] = {a.x, a.y, a.z, a.w, b.x, b.y, b.z, b.w};
    __nv_bfloat16 h[8], l[8];
#pragma unroll
    for (int j = 0; j < 8; j++) {
        h[j] = __float2bfloat16(v[j]);
        l[j] = __float2bfloat16(v[j] - __bfloat162float(h[j]));
    }
    *(uint4*)(hi + i) = *(uint4*)h;
    *(uint4*)(lo + i) = *(uint4*)l;
}

// W [K][N] row-major -> Wt hi/lo [N][K]
__global__ void transpose_split(const float* __restrict__ W,
                                __nv_bfloat16* __restrict__ Thi,
                                __nv_bfloat16* __restrict__ Tlo,
                                int K, int N)
{
    __shared__ float tile[32][33];
    int k0 = blockIdx.y * 32, n0 = blockIdx.x * 32;
    int tx = threadIdx.x, ty = threadIdx.y;
#pragma unroll
    for (int i = ty; i < 32; i += 8)
        tile[i][tx] = W[(size_t)(k0 + i) * N + n0 + tx];
    __syncthreads();
#pragma unroll
    for (int i = ty; i < 32; i += 8) {
        float v = tile[tx][i];
        __nv_bfloat16 h = __float2bfloat16(v);
        float r = v - __bfloat162float(h);
        Thi[(size_t)(n0 + i) * K + k0 + tx] = h;
        Tlo[(size_t)(n0 + i) * K + k0 + tx] = __float2bfloat16(r);
    }
}

// ---------------------------------------------------------------------------
// mma.sync bf16 split GEMM: C = A @ Bt^T + bias (3-pass hi/lo)
// CTA 128x128, BK=32, 8 warps, cp.async 2-stage, ONE barrier per chunk,
// pass-major MMA ordering (16 independent MMAs per pass).
// ---------------------------------------------------------------------------
#define PAD 40
#define MAT_EL (128 * PAD)
#define MAT_B (MAT_EL * 2)
#define STAGE_B (4 * MAT_B)
#define GEMM_SMEM (2 * STAGE_B)
#define NCHUNK (GK / 32)

__global__ __launch_bounds__(256) void tc_gemm_mma(
    const __nv_bfloat16* __restrict__ Ah, const __nv_bfloat16* __restrict__ Al,
    const __nv_bfloat16* __restrict__ Bh, const __nv_bfloat16* __restrict__ Bl,
    const float* __restrict__ bias, float* __restrict__ Co, int N)
{
    extern __shared__ char smem[];
    const uint32_t sb = smem_u32(smem);
    const int tid = threadIdx.x;
    const int wid = tid >> 5, lane = tid & 31;
    const int warp_m = wid >> 1, warp_n = wid & 1;
    const int m0 = blockIdx.y * 128, n0 = blockIdx.x * 128;

    const __nv_bfloat16* srcs[4] = {
        Ah + (size_t)m0 * GK, Al + (size_t)m0 * GK,
        Bh + (size_t)n0 * GK, Bl + (size_t)n0 * GK };

    auto prefetch = [&](int c, int stage) {
        const int k0 = c * 32;
        const uint32_t so = sb + stage * STAGE_B;
#pragma unroll
        for (int msel = 0; msel < 4; msel++) {
#pragma unroll
            for (int i = 0; i < 2; i++) {
                int idx = tid + i * 256;
                int r = idx >> 2, seg = idx & 3;
                uint32_t dst = so + msel * MAT_B + (uint32_t)(r * PAD + seg * 8) * 2;
                cp_async16(dst, srcs[msel] + (size_t)r * GK + k0 + seg * 8);
            }
        }
    };

    float acc[2][8][4];
#pragma unroll
    for (int a = 0; a < 2; a++)
#pragma unroll
        for (int b = 0; b < 8; b++)
#pragma unroll
            for (int c = 0; c < 4; c++) acc[a][b][c] = 0.f;

    prefetch(0, 0);
    cp_commit();

    const int a_row = (lane & 15);
    const int a_col8 = (lane >> 4) << 3;
    const int b_tile = lane >> 3;
    const int b_rin = lane & 7;
    const int b_nrow = ((b_tile >> 1) << 3) + b_rin;
    const int b_kcol = (b_tile & 1) << 3;

    for (int c = 0; c < NCHUNK; c++) {
        const int stage = c & 1;
        cp_wait<0>();                 // wait this chunk's data (only group in flight)
        __syncthreads();              // data visible; prev-chunk reads of other stage done
        if (c + 1 < NCHUNK) { prefetch(c + 1, stage ^ 1); cp_commit(); }

        const uint32_t so = sb + stage * STAGE_B;
#pragma unroll
        for (int ks = 0; ks < 2; ks++) {
            uint32_t aH[2][4], aL[2][4], bH[4][4], bL[4][4];
#pragma unroll
            for (int mi = 0; mi < 2; mi++) {
                uint32_t off = (uint32_t)((warp_m * 32 + mi * 16 + a_row) * PAD
                                          + ks * 16 + a_col8) * 2;
                ldm_x4(aH[mi], so + 0 * MAT_B + off);
                ldm_x4(aL[mi], so + 1 * MAT_B + off);
            }
#pragma unroll
            for (int nj = 0; nj < 4; nj++) {
                uint32_t off = (uint32_t)((warp_n * 64 + nj * 16 + b_nrow) * PAD
                                          + ks * 16 + b_kcol) * 2;
                ldm_x4(bH[nj], so + 2 * MAT_B + off);
                ldm_x4(bL[nj], so + 3 * MAT_B + off);
            }
            // pass-major: 16 independent MMAs per pass -> RAW distance 32
#pragma unroll
            for (int mi = 0; mi < 2; mi++)
#pragma unroll
                for (int nj = 0; nj < 4; nj++) {
                    mma_bf16(acc[mi][nj * 2],     aH[mi], bH[nj][0], bH[nj][1]);
                    mma_bf16(acc[mi][nj * 2 + 1], aH[mi], bH[nj][2], bH[nj][3]);
                }
#pragma unroll
            for (int mi = 0; mi < 2; mi++)
#pragma unroll
                for (int nj = 0; nj < 4; nj++) {
                    mma_bf16(acc[mi][nj * 2],     aH[mi], bL[nj][0], bL[nj][1]);
                    mma_bf16(acc[mi][nj * 2 + 1], aH[mi], bL[nj][2], bL[nj][3]);
                }
#pragma unroll
            for (int mi = 0; mi < 2; mi++)
#pragma unroll
                for (int nj = 0; nj < 4; nj++) {
                    mma_bf16(acc[mi][nj * 2],     aL[mi], bH[nj][0], bH[nj][1]);
                    mma_bf16(acc[mi][nj * 2 + 1], aL[mi], bH[nj][2], bH[nj][3]);
                }
        }
    }

    const int r_base = m0 + warp_m * 32 + (lane >> 2);
    const int c_base = n0 + warp_n * 64 + (lane & 3) * 2;
#pragma unroll
    for (int mi = 0; mi < 2; mi++) {
#pragma unroll
        for (int nj8 = 0; nj8 < 8; nj8++) {
            int col = c_base + nj8 * 8;
            float b0 = __ldg(bias + col), b1 = __ldg(bias + col + 1);
            int r0 = r_base + mi * 16;
            Co[(size_t)r0 * N + col]           = acc[mi][nj8][0] + b0;
            Co[(size_t)r0 * N + col + 1]       = acc[mi][nj8][1] + b1;
            Co[(size_t)(r0 + 8) * N + col]     = acc[mi][nj8][2] + b0;
            Co[(size_t)(r0 + 8) * N + col + 1] = acc[mi][nj8][3] + b1;
        }
    }
}

// ---------------------------------------------------------------------------
// Tensor-core causal flash attention (mma.sync bf16, hi/lo split both MMAs).
// Epilogue writes y directly as bf16 hi/lo (fused split for proj GEMM).
// ---------------------------------------------------------------------------
#define PADA 72
#define KTB  9216  // one [64][72] bf16 tile

__global__ __launch_bounds__(256) void flash_mma_kernel(
    const float* __restrict__ qkv,
    __nv_bfloat16* __restrict__ yhi, __nv_bfloat16* __restrict__ ylo)
{
    __shared__ __align__(16) char smem[36864];
    const uint32_t sb = smem_u32(smem);
    const int tid = threadIdx.x;
    const int wid = tid >> 5, lane = tid & 31;
    const int bh = blockIdx.x, b = bh >> 4, h = bh & 15;
    const int qt = (T_ / 128 - 1) - blockIdx.y;  // long CTAs first
    const int q0 = qt * 128;
    const float* base = qkv + (size_t)b * T_ * C3;

    // ---- stage Q (scaled by 1/8) as hi/lo bf16 ----
    {
        const int r = tid >> 1;
        const int cb = (tid & 1) * 32;
        const float* qp = base + (size_t)(q0 + r) * C3 + h * D_ + cb;
#pragma unroll
        for (int i = 0; i < 8; i++) {
            float4 v = *(const float4*)(qp + i * 4);
            v.x *= 0.125f; v.y *= 0.125f; v.z *= 0.125f; v.w *= 0.125f;
            uint32_t h0, l0, h1, l1;
            split_pair(v.x, v.y, h0, l0);
            split_pair(v.z, v.w, h1, l1);
            uint32_t off = (uint32_t)(r * PADA + cb + i * 4) * 2;
            *(uint32_t*)(smem + off)             = h0;
            *(uint32_t*)(smem + off + 4)         = h1;
            *(uint32_t*)(smem + 18432 + off)     = l0;
            *(uint32_t*)(smem + 18432 + off + 4) = l1;
        }
    }
    __syncthreads();

    const int a_row = lane & 15;
    const int a_col8 = (lane >> 4) << 3;
    const int b_tile = lane >> 3;
    const int b_nrow = ((b_tile >> 1) << 3) + (lane & 7);
    const int b_kcol = (b_tile & 1) << 3;

    uint32_t aQh[4][4], aQl[4][4];
#pragma unroll
    for (int ks = 0; ks < 4; ks++) {
        uint32_t off = (uint32_t)((wid * 16 + a_row) * PADA + ks * 16 + a_col8) * 2;
        ldm_x4(aQh[ks], sb + off);
        ldm_x4(aQl[ks], sb + 18432 + off);
    }

    float oacc[8][4];
#pragma unroll
    for (int i = 0; i < 8; i++)
#pragma unroll
        for (int j = 0; j < 4; j++) oacc[i][j] = 0.f;
    float mrow[2] = {-1e30f, -1e30f};
    float lrow[2] = {0.f, 0.f};

    const int ntiles = 2 * (qt + 1);
    for (int kt = 0; kt < ntiles; kt++) {
        const int k0 = kt * 64;
        __syncthreads();

        // ---- fill K hi/lo [key][dim] and Vt hi/lo [dim][key] ----
#pragma unroll
        for (int i = 0; i < 4; i++) {
            int ii = tid + i * 256;
            int kr = ii >> 4;
            int c4 = (ii & 15) * 4;
            const float* kp = base + (size_t)(k0 + kr) * C3 + C_ + h * D_ + c4;
            float4 kv = *(const float4*)kp;
            uint32_t h0, l0, h1, l1;
            split_pair(kv.x, kv.y, h0, l0);
            split_pair(kv.z, kv.w, h1, l1);
            uint32_t off = (uint32_t)(kr * PADA + c4) * 2;
            *(uint32_t*)(smem + off)           = h0;
            *(uint32_t*)(smem + off + 4)       = h1;
            *(uint32_t*)(smem + KTB + off)     = l0;
            *(uint32_t*)(smem + KTB + off + 4) = l1;

            float4 vv = *(const float4*)(kp + C_);
            float ve[4] = {vv.x, vv.y, vv.z, vv.w};
#pragma unroll
            for (int j = 0; j < 4; j++) {
                __nv_bfloat16 hh = __float2bfloat16(ve[j]);
                __nv_bfloat16 ll = __float2bfloat16(ve[j] - __bfloat162float(hh));
                uint32_t vo = (uint32_t)((c4 + j) * PADA + kr) * 2;
                *(__nv_bfloat16*)(smem + 2 * KTB + vo) = hh;
                *(__nv_bfloat16*)(smem + 3 * KTB + vo) = ll;
            }
        }
        __syncthreads();

        // ---- S = Q @ K^T (3-pass) ----
        float sacc[8][4];
#pragma unroll
        for (int i = 0; i < 8; i++)
#pragma unroll
            for (int j = 0; j < 4; j++) sacc[i][j] = 0.f;
#pragma unroll
        for (int ks = 0; ks < 4; ks++) {
            uint32_t bH[4], bL[4];
#pragma unroll
            for (int nj = 0; nj < 4; nj++) {
                uint32_t off = (uint32_t)((nj * 16 + b_nrow) * PADA
                                          + ks * 16 + b_kcol) * 2;
                ldm_x4(bH, sb + off);
                ldm_x4(bL, sb + KTB + off);
                mma_bf16(sacc[nj * 2],     aQh[ks], bH[0], bH[1]);
                mma_bf16(sacc[nj * 2 + 1], aQh[ks], bH[2], bH[3]);
                mma_bf16(sacc[nj * 2],     aQh[ks], bL[0], bL[1]);
                mma_bf16(sacc[nj * 2 + 1], aQh[ks], bL[2], bL[3]);
                mma_bf16(sacc[nj * 2],     aQl[ks], bH[0], bH[1]);
                mma_bf16(sacc[nj * 2 + 1], aQl[ks], bH[2], bH[3]);
            }
        }

        // ---- causal mask (last two tiles only) ----
        if (k0 >= q0) {
            const int qg = q0 + wid * 16 + (lane >> 2);
            const int cg = k0 + (lane & 3) * 2;
#pragma unroll
            for (int nb = 0; nb < 8; nb++) {
                int col = cg + nb * 8;
                if (col > qg)          sacc[nb][0] = -1e30f;
                if (col + 1 > qg)      sacc[nb][1] = -1e30f;
                if (col > qg + 8)      sacc[nb][2] = -1e30f;
                if (col + 1 > qg + 8)  sacc[nb][3] = -1e30f;
            }
        }

        // ---- online softmax ----
        float mn0 = mrow[0], mn1 = mrow[1];
#pragma unroll
        for (int nb = 0; nb < 8; nb++) {
            mn0 = fmaxf(mn0, fmaxf(sacc[nb][0], sacc[nb][1]));
            mn1 = fmaxf(mn1, fmaxf(sacc[nb][2], sacc[nb][3]));
        }
        mn0 = fmaxf(mn0, __shfl_xor_sync(0xFFFFFFFF, mn0, 1));
        mn0 = fmaxf(mn0, __shfl_xor_sync(0xFFFFFFFF, mn0, 2));
        mn1 = fmaxf(mn1, __shfl_xor_sync(0xFFFFFFFF, mn1, 1));
        mn1 = fmaxf(mn1, __shfl_xor_sync(0xFFFFFFFF, mn1, 2));
        const float corr0 = __expf(mrow[0] - mn0);
        const float corr1 = __expf(mrow[1] - mn1);
        mrow[0] = mn0; mrow[1] = mn1;

        float ps0 = 0.f, ps1 = 0.f;
#pragma unroll
        for (int nb = 0; nb < 8; nb++) {
            sacc[nb][0] = __expf(sacc[nb][0] - mn0);
            sacc[nb][1] = __expf(sacc[nb][1] - mn0);
            sacc[nb][2] = __expf(sacc[nb][2] - mn1);
            sacc[nb][3] = __expf(sacc[nb][3] - mn1);
            ps0 += sacc[nb][0] + sacc[nb][1];
            ps1 += sacc[nb][2] + sacc[nb][3];
        }
        ps0 += __shfl_xor_sync(0xFFFFFFFF, ps0, 1);
        ps0 += __shfl_xor_sync(0xFFFFFFFF, ps0, 2);
        ps1 += __shfl_xor_sync(0xFFFFFFFF, ps1, 1);
        ps1 += __shfl_xor_sync(0xFFFFFFFF, ps1, 2);
        lrow[0] = lrow[0] * corr0 + ps0;
        lrow[1] = lrow[1] * corr1 + ps1;
#pragma unroll
        for (int nb = 0; nb < 8; nb++) {
            oacc[nb][0] *= corr0; oacc[nb][1] *= corr0;
            oacc[nb][2] *= corr1; oacc[nb][3] *= corr1;
        }

        // ---- O += P @ V (3-pass) ----
#pragma unroll
        for (int ks = 0; ks < 4; ks++) {
            uint32_t pH[4], pL[4];
            split_pair(sacc[2 * ks][0],     sacc[2 * ks][1],     pH[0], pL[0]);
            split_pair(sacc[2 * ks][2],     sacc[2 * ks][3],     pH[1], pL[1]);
            split_pair(sacc[2 * ks + 1][0], sacc[2 * ks + 1][1], pH[2], pL[2]);
            split_pair(sacc[2 * ks + 1][2], sacc[2 * ks + 1][3], pH[3], pL[3]);
#pragma unroll
            for (int nj = 0; nj < 4; nj++) {
                uint32_t bH[4], bL[4];
                uint32_t off = (uint32_t)((nj * 16 + b_nrow) * PADA
                                          + ks * 16 + b_kcol) * 2;
                ldm_x4(bH, sb + 2 * KTB + off);
                ldm_x4(bL, sb + 3 * KTB + off);
                mma_bf16(oacc[nj * 2],     pH, bH[0], bH[1]);
                mma_bf16(oacc[nj * 2 + 1], pH, bH[2], bH[3]);
                mma_bf16(oacc[nj * 2],     pH, bL[0], bL[1]);
                mma_bf16(oacc[nj * 2 + 1], pH, bL[2], bL[3]);
                mma_bf16(oacc[nj * 2],     pL, bH[0], bH[1]);
                mma_bf16(oacc[nj * 2 + 1], pL, bH[2], bH[3]);
            }
        }
    }

    // ---- normalize and write y as bf16 hi/lo (fused split for proj GEMM) ----
    const float inv0 = 1.f / lrow[0];
    const float inv1 = 1.f / lrow[1];
    const int rg = q0 + wid * 16 + (lane >> 2);
    const size_t e0 = ((size_t)b * T_ + rg) * C_ + h * D_ + (lane & 3) * 2;
#pragma unroll
    for (int nb = 0; nb < 8; nb++) {
        uint32_t h0, l0, h1, l1;
        split_pair(oacc[nb][0] * inv0, oacc[nb][1] * inv0, h0, l0);
        split_pair(oacc[nb][2] * inv1, oacc[nb][3] * inv1, h1, l1);
        *(uint32_t*)(yhi + e0 + nb * 8)          = h0;
        *(uint32_t*)(ylo + e0 + nb * 8)          = l0;
        *(uint32_t*)(yhi + e0 + 8 * C_ + nb * 8) = h1;
        *(uint32_t*)(ylo + e0 + 8 * C_ + nb * 8) = l1;
    }
}

// ---------------------------------------------------------------------------
extern "C" void kernel_launch(void* const* d_in, const int* in_sizes, int n_in,
                              void* d_out, int out_size)
{
    const float* x      = (const float*)d_in[0];
    const float* W_attn = (const float*)d_in[1];
    const float* b_attn = (const float*)d_in[2];
    const float* W_proj = (const float*)d_in[3];
    const float* b_proj = (const float*)d_in[4];
    float* out = (float*)d_out;

    float *qkv_p;
    __nv_bfloat16 *xhi, *xlo, *yhi, *ylo, *wahi, *walo, *wphi, *wplo;
    cudaGetSymbolAddress((void**)&qkv_p, g_qkv);
    cudaGetSymbolAddress((void**)&xhi, g_xhi);
    cudaGetSymbolAddress((void**)&xlo, g_xlo);
    cudaGetSymbolAddress((void**)&yhi, g_yhi);
    cudaGetSymbolAddress((void**)&ylo, g_ylo);
    cudaGetSymbolAddress((void**)&wahi, g_wahi);
    cudaGetSymbolAddress((void**)&walo, g_walo);
    cudaGetSymbolAddress((void**)&wphi, g_wphi);
    cudaGetSymbolAddress((void**)&wplo, g_wplo);

    cudaFuncSetAttribute(tc_gemm_mma, cudaFuncAttributeMaxDynamicSharedMemorySize,
                         GEMM_SMEM);

    const int NTOK_EL = M_TOK * C_;

    // 1) split x -> bf16 hi/lo
    split_kernel<<<NTOK_EL / 8 / 256, 256>>>(x, xhi, xlo, NTOK_EL);
    // 2) transpose+split weights
    transpose_split<<<dim3(C3 / 32, C_ / 32), dim3(32, 8)>>>(W_attn, wahi, walo, C_, C3);
    transpose_split<<<dim3(C_ / 32, C_ / 32), dim3(32, 8)>>>(W_proj, wphi, wplo, C_, C_);
    // 3) QKV GEMM (tensor cores)
    tc_gemm_mma<<<dim3(C3 / 128, M_TOK / 128), 256, GEMM_SMEM>>>(
        xhi, xlo, wahi, walo, b_attn, qkv_p, C3);
    // 4) causal flash attention (tensor cores), y split fused in epilogue
    flash_mma_kernel<<<dim3(B_ * H_, T_ / 128), 256>>>(qkv_p, yhi, ylo);
    // 5) proj GEMM (tensor cores) -> d_out
    tc_gemm_mma<<<dim3(C_ / 128, M_TOK / 128), 256, GEMM_SMEM>>>(
        yhi, ylo, wphi, wplo, b_proj, out, C_);
}

// round 7
// speedup vs baseline: 1.2171x; 1.2171x over previous
#include <cuda_runtime.h>
#include <cuda_bf16.h>
#include <cstdint>
#include <cstddef>

// Problem constants
#define B_  4
#define T_  2048
#define C_  1024
#define H_  16
#define D_  64
#define M_TOK (B_ * T_)      // 8192
#define C3 (3 * C_)          // 3072
#define GK 1024              // K of both GEMMs

// ---------------------------------------------------------------------------
// Scratch (device globals; allocation in kernel_launch is forbidden)
// ---------------------------------------------------------------------------
__device__ float g_qkv[(size_t)M_TOK * C3];  // [B*T, 3C] fp32
__device__ __nv_bfloat16 g_xhi[(size_t)M_TOK * C_];
__device__ __nv_bfloat16 g_xlo[(size_t)M_TOK * C_];
__device__ __nv_bfloat16 g_yhi[(size_t)M_TOK * C_];
__device__ __nv_bfloat16 g_ylo[(size_t)M_TOK * C_];
__device__ __nv_bfloat16 g_wahi[(size_t)C3 * C_];  // W_attn^T [3C][C]
__device__ __nv_bfloat16 g_walo[(size_t)C3 * C_];
__device__ __nv_bfloat16 g_wphi[(size_t)C_ * C_];  // W_proj^T [C][C]
__device__ __nv_bfloat16 g_wplo[(size_t)C_ * C_];

// ---------------------------------------------------------------------------
// PTX helpers
// ---------------------------------------------------------------------------
__device__ __forceinline__ uint32_t smem_u32(const void* p) {
    uint32_t a;
    asm("{ .reg .u64 t; cvta.to.shared.u64 t, %1; cvt.u32.u64 %0, t; }"
        : "=r"(a) : "l"(p));
    return a;
}
__device__ __forceinline__ void cp_async16(uint32_t dst, const void* src) {
    asm volatile("cp.async.cg.shared.global [%0], [%1], 16;"
                 :: "r"(dst), "l"(src) : "memory");
}
__device__ __forceinline__ void cp_commit() {
    asm volatile("cp.async.commit_group;" ::: "memory");
}
template <int N>
__device__ __forceinline__ void cp_wait() {
    asm volatile("cp.async.wait_group %0;" :: "n"(N) : "memory");
}
__device__ __forceinline__ void ldm_x4(uint32_t* r, uint32_t addr) {
    asm volatile("ldmatrix.sync.aligned.m8n8.x4.shared.b16 {%0,%1,%2,%3}, [%4];"
                 : "=r"(r[0]), "=r"(r[1]), "=r"(r[2]), "=r"(r[3]) : "r"(addr));
}
__device__ __forceinline__ void ldm_x4_trans(uint32_t* r, uint32_t addr) {
    asm volatile("ldmatrix.sync.aligned.m8n8.x4.trans.shared.b16 {%0,%1,%2,%3}, [%4];"
                 : "=r"(r[0]), "=r"(r[1]), "=r"(r[2]), "=r"(r[3]) : "r"(addr));
}
// volatile variant: reproduces round-5 GEMM register allocation (122 regs, 2 CTA/SM)
__device__ __forceinline__ void mma_bf16_v(float* d, const uint32_t* a,
                                           uint32_t b0, uint32_t b1) {
    asm volatile(
        "mma.sync.aligned.m16n8k16.row.col.f32.bf16.bf16.f32 "
        "{%0,%1,%2,%3}, {%4,%5,%6,%7}, {%8,%9}, {%0,%1,%2,%3};"
        : "+f"(d[0]), "+f"(d[1]), "+f"(d[2]), "+f"(d[3])
        : "r"(a[0]), "r"(a[1]), "r"(a[2]), "r"(a[3]), "r"(b0), "r"(b1));
}
__device__ __forceinline__ void mma_bf16(float* d, const uint32_t* a,
                                         uint32_t b0, uint32_t b1) {
    asm("mma.sync.aligned.m16n8k16.row.col.f32.bf16.bf16.f32 "
        "{%0,%1,%2,%3}, {%4,%5,%6,%7}, {%8,%9}, {%0,%1,%2,%3};"
        : "+f"(d[0]), "+f"(d[1]), "+f"(d[2]), "+f"(d[3])
        : "r"(a[0]), "r"(a[1]), "r"(a[2]), "r"(a[3]), "r"(b0), "r"(b1));
}
__device__ __forceinline__ uint32_t b2u(__nv_bfloat162 v) {
    return *reinterpret_cast<uint32_t*>(&v);
}
__device__ __forceinline__ void split_pair(float x, float y,
                                           uint32_t& hi, uint32_t& lo) {
    __nv_bfloat162 h = __float22bfloat162_rn(make_float2(x, y));
    float2 hf = __bfloat1622float2(h);
    __nv_bfloat162 l = __float22bfloat162_rn(make_float2(x - hf.x, y - hf.y));
    hi = b2u(h); lo = b2u(l);
}

// ---------------------------------------------------------------------------
// Conversion kernels
// ---------------------------------------------------------------------------
__global__ void split_kernel(const float* __restrict__ in,
                             __nv_bfloat16* __restrict__ hi,
                             __nv_bfloat16* __restrict__ lo, int n)
{
    int i = (blockIdx.x * blockDim.x + threadIdx.x) * 8;
    if (i >= n) return;
    float4 a = *(const float4*)(in + i);
    float4 b = *(const float4*)(in + i + 4);
    float v[8] = {a.x, a.y, a.z, a.w, b.x, b.y, b.z, b.w};
    __nv_bfloat16 h[8], l[8];
#pragma unroll
    for (int j = 0; j < 8; j++) {
        h[j] = __float2bfloat16(v[j]);
        l[j] = __float2bfloat16(v[j] - __bfloat162float(h[j]));
    }
    *(uint4*)(hi + i) = *(uint4*)h;
    *(uint4*)(lo + i) = *(uint4*)l;
}

// W [K][N] row-major -> Wt hi/lo [N][K]
__global__ void transpose_split(const float* __restrict__ W,
                                __nv_bfloat16* __restrict__ Thi,
                                __nv_bfloat16* __restrict__ Tlo,
                                int K, int N)
{
    __shared__ float tile[32][33];
    int k0 = blockIdx.y * 32, n0 = blockIdx.x * 32;
    int tx = threadIdx.x, ty = threadIdx.y;
#pragma unroll
    for (int i = ty; i < 32; i += 8)
        tile[i][tx] = W[(size_t)(k0 + i) * N + n0 + tx];
    __syncthreads();
#pragma unroll
    for (int i = ty; i < 32; i += 8) {
        float v = tile[tx][i];
        __nv_bfloat16 h = __float2bfloat16(v);
        float r = v - __bfloat162float(h);
        Thi[(size_t)(n0 + i) * K + k0 + tx] = h;
        Tlo[(size_t)(n0 + i) * K + k0 + tx] = __float2bfloat16(r);
    }
}

// ---------------------------------------------------------------------------
// mma.sync bf16 split GEMM — EXACT round-5 version (501 us QKV, 2 CTAs/SM)
// ---------------------------------------------------------------------------
#define PAD 40
#define MAT_EL (128 * PAD)
#define MAT_B (MAT_EL * 2)
#define STAGE_B (4 * MAT_B)
#define GEMM_SMEM (2 * STAGE_B)
#define NCHUNK (GK / 32)

__global__ __launch_bounds__(256) void tc_gemm_mma(
    const __nv_bfloat16* __restrict__ Ah, const __nv_bfloat16* __restrict__ Al,
    const __nv_bfloat16* __restrict__ Bh, const __nv_bfloat16* __restrict__ Bl,
    const float* __restrict__ bias, float* __restrict__ Co, int N)
{
    extern __shared__ char smem[];
    const uint32_t sb = smem_u32(smem);
    const int tid = threadIdx.x;
    const int wid = tid >> 5, lane = tid & 31;
    const int warp_m = wid >> 1, warp_n = wid & 1;
    const int m0 = blockIdx.y * 128, n0 = blockIdx.x * 128;

    const __nv_bfloat16* srcs[4] = {
        Ah + (size_t)m0 * GK, Al + (size_t)m0 * GK,
        Bh + (size_t)n0 * GK, Bl + (size_t)n0 * GK };

    auto prefetch = [&](int c, int stage) {
        const int k0 = c * 32;
        const uint32_t so = sb + stage * STAGE_B;
#pragma unroll
        for (int msel = 0; msel < 4; msel++) {
#pragma unroll
            for (int i = 0; i < 2; i++) {
                int idx = tid + i * 256;
                int r = idx >> 2, seg = idx & 3;
                uint32_t dst = so + msel * MAT_B + (uint32_t)(r * PAD + seg * 8) * 2;
                cp_async16(dst, srcs[msel] + (size_t)r * GK + k0 + seg * 8);
            }
        }
    };

    float acc[2][8][4];
#pragma unroll
    for (int a = 0; a < 2; a++)
#pragma unroll
        for (int b = 0; b < 8; b++)
#pragma unroll
            for (int c = 0; c < 4; c++) acc[a][b][c] = 0.f;

    prefetch(0, 0);
    cp_commit();

    const int a_row = (lane & 15);
    const int a_col8 = (lane >> 4) << 3;
    const int b_tile = lane >> 3;
    const int b_rin = lane & 7;
    const int b_nrow = ((b_tile >> 1) << 3) + b_rin;
    const int b_kcol = (b_tile & 1) << 3;

    for (int c = 0; c < NCHUNK; c++) {
        const int stage = c & 1;
        if (c + 1 < NCHUNK) { prefetch(c + 1, stage ^ 1); cp_commit(); }
        if (c + 1 < NCHUNK) cp_wait<1>(); else cp_wait<0>();
        __syncthreads();

        const uint32_t so = sb + stage * STAGE_B;
#pragma unroll
        for (int ks = 0; ks < 2; ks++) {
            uint32_t aH[2][4], aL[2][4], bH[4][4], bL[4][4];
#pragma unroll
            for (int mi = 0; mi < 2; mi++) {
                uint32_t off = (uint32_t)((warp_m * 32 + mi * 16 + a_row) * PAD
                                          + ks * 16 + a_col8) * 2;
                ldm_x4(aH[mi], so + 0 * MAT_B + off);
                ldm_x4(aL[mi], so + 1 * MAT_B + off);
            }
#pragma unroll
            for (int nj = 0; nj < 4; nj++) {
                uint32_t off = (uint32_t)((warp_n * 64 + nj * 16 + b_nrow) * PAD
                                          + ks * 16 + b_kcol) * 2;
                ldm_x4(bH[nj], so + 2 * MAT_B + off);
                ldm_x4(bL[nj], so + 3 * MAT_B + off);
            }
#pragma unroll
            for (int mi = 0; mi < 2; mi++)
#pragma unroll
                for (int nj = 0; nj < 4; nj++) {
                    mma_bf16_v(acc[mi][nj * 2],     aH[mi], bH[nj][0], bH[nj][1]);
                    mma_bf16_v(acc[mi][nj * 2 + 1], aH[mi], bH[nj][2], bH[nj][3]);
                    mma_bf16_v(acc[mi][nj * 2],     aH[mi], bL[nj][0], bL[nj][1]);
                    mma_bf16_v(acc[mi][nj * 2 + 1], aH[mi], bL[nj][2], bL[nj][3]);
                    mma_bf16_v(acc[mi][nj * 2],     aL[mi], bH[nj][0], bH[nj][1]);
                    mma_bf16_v(acc[mi][nj * 2 + 1], aL[mi], bH[nj][2], bH[nj][3]);
                }
        }
        __syncthreads();
    }

    const int r_base = m0 + warp_m * 32 + (lane >> 2);
    const int c_base = n0 + warp_n * 64 + (lane & 3) * 2;
#pragma unroll
    for (int mi = 0; mi < 2; mi++) {
#pragma unroll
        for (int nj8 = 0; nj8 < 8; nj8++) {
            int col = c_base + nj8 * 8;
            float b0 = __ldg(bias + col), b1 = __ldg(bias + col + 1);
            int r0 = r_base + mi * 16;
            Co[(size_t)r0 * N + col]           = acc[mi][nj8][0] + b0;
            Co[(size_t)r0 * N + col + 1]       = acc[mi][nj8][1] + b1;
            Co[(size_t)(r0 + 8) * N + col]     = acc[mi][nj8][2] + b0;
            Co[(size_t)(r0 + 8) * N + col + 1] = acc[mi][nj8][3] + b1;
        }
    }
}

// ---------------------------------------------------------------------------
// Tensor-core causal flash attention.
// V kept in natural [key][dim] layout; P@V B-operand loaded via ldmatrix.trans
// (no scatter transpose in the fill loop). Epilogue writes y as bf16 hi/lo.
// ---------------------------------------------------------------------------
#define PADA 72
#define KTB  9216  // one [64][72] bf16 tile

__global__ __launch_bounds__(256) void flash_mma_kernel(
    const float* __restrict__ qkv,
    __nv_bfloat16* __restrict__ yhi, __nv_bfloat16* __restrict__ ylo)
{
    __shared__ __align__(16) char smem[36864];
    const uint32_t sb = smem_u32(smem);
    const int tid = threadIdx.x;
    const int wid = tid >> 5, lane = tid & 31;
    const int bh = blockIdx.x, b = bh >> 4, h = bh & 15;
    const int qt = (T_ / 128 - 1) - blockIdx.y;  // long CTAs first
    const int q0 = qt * 128;
    const float* base = qkv + (size_t)b * T_ * C3;

    // ---- stage Q (scaled by 1/8) as hi/lo bf16 ----
    {
        const int r = tid >> 1;
        const int cb = (tid & 1) * 32;
        const float* qp = base + (size_t)(q0 + r) * C3 + h * D_ + cb;
#pragma unroll
        for (int i = 0; i < 8; i++) {
            float4 v = *(const float4*)(qp + i * 4);
            v.x *= 0.125f; v.y *= 0.125f; v.z *= 0.125f; v.w *= 0.125f;
            uint32_t h0, l0, h1, l1;
            split_pair(v.x, v.y, h0, l0);
            split_pair(v.z, v.w, h1, l1);
            uint32_t off = (uint32_t)(r * PADA + cb + i * 4) * 2;
            *(uint32_t*)(smem + off)             = h0;
            *(uint32_t*)(smem + off + 4)         = h1;
            *(uint32_t*)(smem + 18432 + off)     = l0;
            *(uint32_t*)(smem + 18432 + off + 4) = l1;
        }
    }
    __syncthreads();

    const int a_row = lane & 15;
    const int a_col8 = (lane >> 4) << 3;
    const int b_tile = lane >> 3;
    const int b_nrow = ((b_tile >> 1) << 3) + (lane & 7);
    const int b_kcol = (b_tile & 1) << 3;
    // trans-ldmatrix addressing for V in [key][dim] layout:
    //   quadrants q0..q3 = (n0-7,k0-7),(n0-7,k8-15),(n8-15,k0-7),(n8-15,k8-15)
    const int v_krow = ((b_tile & 1) << 3) + (lane & 7);  // key row within 16
    const int v_ncol = (b_tile >> 1) << 3;                // dim col within 16

    uint32_t aQh[4][4], aQl[4][4];
#pragma unroll
    for (int ks = 0; ks < 4; ks++) {
        uint32_t off = (uint32_t)((wid * 16 + a_row) * PADA + ks * 16 + a_col8) * 2;
        ldm_x4(aQh[ks], sb + off);
        ldm_x4(aQl[ks], sb + 18432 + off);
    }

    float oacc[8][4];
#pragma unroll
    for (int i = 0; i < 8; i++)
#pragma unroll
        for (int j = 0; j < 4; j++) oacc[i][j] = 0.f;
    float mrow[2] = {-1e30f, -1e30f};
    float lrow[2] = {0.f, 0.f};

    const int ntiles = 2 * (qt + 1);
    for (int kt = 0; kt < ntiles; kt++) {
        const int k0 = kt * 64;
        __syncthreads();

        // ---- fill K hi/lo and V hi/lo, both [key][dim] (coalesced stores) ----
#pragma unroll
        for (int i = 0; i < 4; i++) {
            int ii = tid + i * 256;
            int kr = ii >> 4;
            int c4 = (ii & 15) * 4;
            const float* kp = base + (size_t)(k0 + kr) * C3 + C_ + h * D_ + c4;
            uint32_t off = (uint32_t)(kr * PADA + c4) * 2;

            float4 kv = *(const float4*)kp;
            uint32_t h0, l0, h1, l1;
            split_pair(kv.x, kv.y, h0, l0);
            split_pair(kv.z, kv.w, h1, l1);
            *(uint32_t*)(smem + off)           = h0;
            *(uint32_t*)(smem + off + 4)       = h1;
            *(uint32_t*)(smem + KTB + off)     = l0;
            *(uint32_t*)(smem + KTB + off + 4) = l1;

            float4 vv = *(const float4*)(kp + C_);
            split_pair(vv.x, vv.y, h0, l0);
            split_pair(vv.z, vv.w, h1, l1);
            *(uint32_t*)(smem + 2 * KTB + off)     = h0;
            *(uint32_t*)(smem + 2 * KTB + off + 4) = h1;
            *(uint32_t*)(smem + 3 * KTB + off)     = l0;
            *(uint32_t*)(smem + 3 * KTB + off + 4) = l1;
        }
        __syncthreads();

        // ---- S = Q @ K^T (3-pass) ----
        float sacc[8][4];
#pragma unroll
        for (int i = 0; i < 8; i++)
#pragma unroll
            for (int j = 0; j < 4; j++) sacc[i][j] = 0.f;
#pragma unroll
        for (int ks = 0; ks < 4; ks++) {
            uint32_t bH[4], bL[4];
#pragma unroll
            for (int nj = 0; nj < 4; nj++) {
                uint32_t off = (uint32_t)((nj * 16 + b_nrow) * PADA
                                          + ks * 16 + b_kcol) * 2;
                ldm_x4(bH, sb + off);
                ldm_x4(bL, sb + KTB + off);
                mma_bf16(sacc[nj * 2],     aQh[ks], bH[0], bH[1]);
                mma_bf16(sacc[nj * 2 + 1], aQh[ks], bH[2], bH[3]);
                mma_bf16(sacc[nj * 2],     aQh[ks], bL[0], bL[1]);
                mma_bf16(sacc[nj * 2 + 1], aQh[ks], bL[2], bL[3]);
                mma_bf16(sacc[nj * 2],     aQl[ks], bH[0], bH[1]);
                mma_bf16(sacc[nj * 2 + 1], aQl[ks], bH[2], bH[3]);
            }
        }

        // ---- causal mask (last two tiles only) ----
        if (k0 >= q0) {
            const int qg = q0 + wid * 16 + (lane >> 2);
            const int cg = k0 + (lane & 3) * 2;
#pragma unroll
            for (int nb = 0; nb < 8; nb++) {
                int col = cg + nb * 8;
                if (col > qg)          sacc[nb][0] = -1e30f;
                if (col + 1 > qg)      sacc[nb][1] = -1e30f;
                if (col > qg + 8)      sacc[nb][2] = -1e30f;
                if (col + 1 > qg + 8)  sacc[nb][3] = -1e30f;
            }
        }

        // ---- online softmax ----
        float mn0 = mrow[0], mn1 = mrow[1];
#pragma unroll
        for (int nb = 0; nb < 8; nb++) {
            mn0 = fmaxf(mn0, fmaxf(sacc[nb][0], sacc[nb][1]));
            mn1 = fmaxf(mn1, fmaxf(sacc[nb][2], sacc[nb][3]));
        }
        mn0 = fmaxf(mn0, __shfl_xor_sync(0xFFFFFFFF, mn0, 1));
        mn0 = fmaxf(mn0, __shfl_xor_sync(0xFFFFFFFF, mn0, 2));
        mn1 = fmaxf(mn1, __shfl_xor_sync(0xFFFFFFFF, mn1, 1));
        mn1 = fmaxf(mn1, __shfl_xor_sync(0xFFFFFFFF, mn1, 2));
        const float corr0 = __expf(mrow[0] - mn0);
        const float corr1 = __expf(mrow[1] - mn1);
        mrow[0] = mn0; mrow[1] = mn1;

        float ps0 = 0.f, ps1 = 0.f;
#pragma unroll
        for (int nb = 0; nb < 8; nb++) {
            sacc[nb][0] = __expf(sacc[nb][0] - mn0);
            sacc[nb][1] = __expf(sacc[nb][1] - mn0);
            sacc[nb][2] = __expf(sacc[nb][2] - mn1);
            sacc[nb][3] = __expf(sacc[nb][3] - mn1);
            ps0 += sacc[nb][0] + sacc[nb][1];
            ps1 += sacc[nb][2] + sacc[nb][3];
        }
        ps0 += __shfl_xor_sync(0xFFFFFFFF, ps0, 1);
        ps0 += __shfl_xor_sync(0xFFFFFFFF, ps0, 2);
        ps1 += __shfl_xor_sync(0xFFFFFFFF, ps1, 1);
        ps1 += __shfl_xor_sync(0xFFFFFFFF, ps1, 2);
        lrow[0] = lrow[0] * corr0 + ps0;
        lrow[1] = lrow[1] * corr1 + ps1;
#pragma unroll
        for (int nb = 0; nb < 8; nb++) {
            oacc[nb][0] *= corr0; oacc[nb][1] *= corr0;
            oacc[nb][2] *= corr1; oacc[nb][3] *= corr1;
        }

        // ---- O += P @ V (3-pass, V via ldmatrix.trans from [key][dim]) ----
#pragma unroll
        for (int ks = 0; ks < 4; ks++) {
            uint32_t pH[4], pL[4];
            split_pair(sacc[2 * ks][0],     sacc[2 * ks][1],     pH[0], pL[0]);
            split_pair(sacc[2 * ks][2],     sacc[2 * ks][3],     pH[1], pL[1]);
            split_pair(sacc[2 * ks + 1][0], sacc[2 * ks + 1][1], pH[2], pL[2]);
            split_pair(sacc[2 * ks + 1][2], sacc[2 * ks + 1][3], pH[3], pL[3]);
#pragma unroll
            for (int nj = 0; nj < 4; nj++) {
                uint32_t bH[4], bL[4];
                uint32_t off = (uint32_t)((ks * 16 + v_krow) * PADA
                                          + nj * 16 + v_ncol) * 2;
                ldm_x4_trans(bH, sb + 2 * KTB + off);
                ldm_x4_trans(bL, sb + 3 * KTB + off);
                mma_bf16(oacc[nj * 2],     pH, bH[0], bH[1]);
                mma_bf16(oacc[nj * 2 + 1], pH, bH[2], bH[3]);
                mma_bf16(oacc[nj * 2],     pH, bL[0], bL[1]);
                mma_bf16(oacc[nj * 2 + 1], pH, bL[2], bL[3]);
                mma_bf16(oacc[nj * 2],     pL, bH[0], bH[1]);
                mma_bf16(oacc[nj * 2 + 1], pL, bH[2], bH[3]);
            }
        }
    }

    // ---- normalize and write y as bf16 hi/lo (fused split for proj GEMM) ----
    const float inv0 = 1.f / lrow[0];
    const float inv1 = 1.f / lrow[1];
    const int rg = q0 + wid * 16 + (lane >> 2);
    const size_t e0 = ((size_t)b * T_ + rg) * C_ + h * D_ + (lane & 3) * 2;
#pragma unroll
    for (int nb = 0; nb < 8; nb++) {
        uint32_t h0, l0, h1, l1;
        split_pair(oacc[nb][0] * inv0, oacc[nb][1] * inv0, h0, l0);
        split_pair(oacc[nb][2] * inv1, oacc[nb][3] * inv1, h1, l1);
        *(uint32_t*)(yhi + e0 + nb * 8)          = h0;
        *(uint32_t*)(ylo + e0 + nb * 8)          = l0;
        *(uint32_t*)(yhi + e0 + 8 * C_ + nb * 8) = h1;
        *(uint32_t*)(ylo + e0 + 8 * C_ + nb * 8) = l1;
    }
}

// ---------------------------------------------------------------------------
extern "C" void kernel_launch(void* const* d_in, const int* in_sizes, int n_in,
                              void* d_out, int out_size)
{
    const float* x      = (const float*)d_in[0];
    const float* W_attn = (const float*)d_in[1];
    const float* b_attn = (const float*)d_in[2];
    const float* W_proj = (const float*)d_in[3];
    const float* b_proj = (const float*)d_in[4];
    float* out = (float*)d_out;

    float *qkv_p;
    __nv_bfloat16 *xhi, *xlo, *yhi, *ylo, *wahi, *walo, *wphi, *wplo;
    cudaGetSymbolAddress((void**)&qkv_p, g_qkv);
    cudaGetSymbolAddress((void**)&xhi, g_xhi);
    cudaGetSymbolAddress((void**)&xlo, g_xlo);
    cudaGetSymbolAddress((void**)&yhi, g_yhi);
    cudaGetSymbolAddress((void**)&ylo, g_ylo);
    cudaGetSymbolAddress((void**)&wahi, g_wahi);
    cudaGetSymbolAddress((void**)&walo, g_walo);
    cudaGetSymbolAddress((void**)&wphi, g_wphi);
    cudaGetSymbolAddress((void**)&wplo, g_wplo);

    cudaFuncSetAttribute(tc_gemm_mma, cudaFuncAttributeMaxDynamicSharedMemorySize,
                         GEMM_SMEM);

    const int NTOK_EL = M_TOK * C_;

    // 1) split x -> bf16 hi/lo
    split_kernel<<<NTOK_EL / 8 / 256, 256>>>(x, xhi, xlo, NTOK_EL);
    // 2) transpose+split weights
    transpose_split<<<dim3(C3 / 32, C_ / 32), dim3(32, 8)>>>(W_attn, wahi, walo, C_, C3);
    transpose_split<<<dim3(C_ / 32, C_ / 32), dim3(32, 8)>>>(W_proj, wphi, wplo, C_, C_);
    // 3) QKV GEMM (tensor cores)
    tc_gemm_mma<<<dim3(C3 / 128, M_TOK / 128), 256, GEMM_SMEM>>>(
        xhi, xlo, wahi, walo, b_attn, qkv_p, C3);
    // 4) causal flash attention (tensor cores), y split fused in epilogue
    flash_mma_kernel<<<dim3(B_ * H_, T_ / 128), 256>>>(qkv_p, yhi, ylo);
    // 5) proj GEMM (tensor cores) -> d_out
    tc_gemm_mma<<<dim3(C_ / 128, M_TOK / 128), 256, GEMM_SMEM>>>(
        yhi, ylo, wphi, wplo, b_proj, out, C_);
}

// round 8
// speedup vs baseline: 1.2174x; 1.0002x over previous
#include <cuda_runtime.h>
#include <cuda_bf16.h>
#include <cstdint>
#include <cstddef>

// Problem constants
#define B_  4
#define T_  2048
#define C_  1024
#define H_  16
#define D_  64
#define M_TOK (B_ * T_)      // 8192
#define C3 (3 * C_)          // 3072
#define GK 1024              // K of both GEMMs

// ---------------------------------------------------------------------------
// Scratch (device globals; allocation in kernel_launch is forbidden)
// ---------------------------------------------------------------------------
__device__ float g_qkv[(size_t)M_TOK * C3];  // [B*T, 3C] fp32
__device__ __nv_bfloat16 g_xhi[(size_t)M_TOK * C_];
__device__ __nv_bfloat16 g_xlo[(size_t)M_TOK * C_];
__device__ __nv_bfloat16 g_yhi[(size_t)M_TOK * C_];
__device__ __nv_bfloat16 g_ylo[(size_t)M_TOK * C_];
__device__ __nv_bfloat16 g_wahi[(size_t)C3 * C_];  // W_attn^T [3C][C]
__device__ __nv_bfloat16 g_walo[(size_t)C3 * C_];
__device__ __nv_bfloat16 g_wphi[(size_t)C_ * C_];  // W_proj^T [C][C]
__device__ __nv_bfloat16 g_wplo[(size_t)C_ * C_];

// ---------------------------------------------------------------------------
// PTX helpers
// ---------------------------------------------------------------------------
__device__ __forceinline__ uint32_t smem_u32(const void* p) {
    uint32_t a;
    asm("{ .reg .u64 t; cvta.to.shared.u64 t, %1; cvt.u32.u64 %0, t; }"
        : "=r"(a) : "l"(p));
    return a;
}
__device__ __forceinline__ void cp_async16(uint32_t dst, const void* src) {
    asm volatile("cp.async.cg.shared.global [%0], [%1], 16;"
                 :: "r"(dst), "l"(src) : "memory");
}
__device__ __forceinline__ void cp_commit() {
    asm volatile("cp.async.commit_group;" ::: "memory");
}
template <int N>
__device__ __forceinline__ void cp_wait() {
    asm volatile("cp.async.wait_group %0;" :: "n"(N) : "memory");
}
__device__ __forceinline__ void ldm_x4(uint32_t* r, uint32_t addr) {
    asm volatile("ldmatrix.sync.aligned.m8n8.x4.shared.b16 {%0,%1,%2,%3}, [%4];"
                 : "=r"(r[0]), "=r"(r[1]), "=r"(r[2]), "=r"(r[3]) : "r"(addr));
}
__device__ __forceinline__ void ldm_x4_trans(uint32_t* r, uint32_t addr) {
    asm volatile("ldmatrix.sync.aligned.m8n8.x4.trans.shared.b16 {%0,%1,%2,%3}, [%4];"
                 : "=r"(r[0]), "=r"(r[1]), "=r"(r[2]), "=r"(r[3]) : "r"(addr));
}
// volatile variant: keeps ptxas from hoisting loads (regs stay ~122, 2 CTA/SM)
__device__ __forceinline__ void mma_bf16_v(float* d, const uint32_t* a,
                                           uint32_t b0, uint32_t b1) {
    asm volatile(
        "mma.sync.aligned.m16n8k16.row.col.f32.bf16.bf16.f32 "
        "{%0,%1,%2,%3}, {%4,%5,%6,%7}, {%8,%9}, {%0,%1,%2,%3};"
        : "+f"(d[0]), "+f"(d[1]), "+f"(d[2]), "+f"(d[3])
        : "r"(a[0]), "r"(a[1]), "r"(a[2]), "r"(a[3]), "r"(b0), "r"(b1));
}
__device__ __forceinline__ void mma_bf16(float* d, const uint32_t* a,
                                         uint32_t b0, uint32_t b1) {
    asm("mma.sync.aligned.m16n8k16.row.col.f32.bf16.bf16.f32 "
        "{%0,%1,%2,%3}, {%4,%5,%6,%7}, {%8,%9}, {%0,%1,%2,%3};"
        : "+f"(d[0]), "+f"(d[1]), "+f"(d[2]), "+f"(d[3])
        : "r"(a[0]), "r"(a[1]), "r"(a[2]), "r"(a[3]), "r"(b0), "r"(b1));
}
__device__ __forceinline__ uint32_t b2u(__nv_bfloat162 v) {
    return *reinterpret_cast<uint32_t*>(&v);
}
__device__ __forceinline__ void split_pair(float x, float y,
                                           uint32_t& hi, uint32_t& lo) {
    __nv_bfloat162 h = __float22bfloat162_rn(make_float2(x, y));
    float2 hf = __bfloat1622float2(h);
    __nv_bfloat162 l = __float22bfloat162_rn(make_float2(x - hf.x, y - hf.y));
    hi = b2u(h); lo = b2u(l);
}

// ---------------------------------------------------------------------------
// Conversion kernels
// ---------------------------------------------------------------------------
__global__ void split_kernel(const float* __restrict__ in,
                             __nv_bfloat16* __restrict__ hi,
                             __nv_bfloat16* __restrict__ lo, int n)
{
    int i = (blockIdx.x * blockDim.x + threadIdx.x) * 8;
    if (i >= n) return;
    float4 a = *(const float4*)(in + i);
    float4 b = *(const float4*)(in + i + 4);
    float v[8] = {a.x, a.y, a.z, a.w, b.x, b.y, b.z, b.w};
    __nv_bfloat16 h[8], l[8];
#pragma unroll
    for (int j = 0; j < 8; j++) {
        h[j] = __float2bfloat16(v[j]);
        l[j] = __float2bfloat16(v[j] - __bfloat162float(h[j]));
    }
    *(uint4*)(hi + i) = *(uint4*)h;
    *(uint4*)(lo + i) = *(uint4*)l;
}

// W [K][N] row-major -> Wt hi/lo [N][K]
__global__ void transpose_split(const float* __restrict__ W,
                                __nv_bfloat16* __restrict__ Thi,
                                __nv_bfloat16* __restrict__ Tlo,
                                int K, int N)
{
    __shared__ float tile[32][33];
    int k0 = blockIdx.y * 32, n0 = blockIdx.x * 32;
    int tx = threadIdx.x, ty = threadIdx.y;
#pragma unroll
    for (int i = ty; i < 32; i += 8)
        tile[i][tx] = W[(size_t)(k0 + i) * N + n0 + tx];
    __syncthreads();
#pragma unroll
    for (int i = ty; i < 32; i += 8) {
        float v = tile[tx][i];
        __nv_bfloat16 h = __float2bfloat16(v);
        float r = v - __bfloat162float(h);
        Thi[(size_t)(n0 + i) * K + k0 + tx] = h;
        Tlo[(size_t)(n0 + i) * K + k0 + tx] = __float2bfloat16(r);
    }
}

// ---------------------------------------------------------------------------
// mma.sync bf16 split GEMM — round-5 structure, PASS-MAJOR MMA ordering
// (volatile asm keeps register allocation; 16-MMA RAW distance per pass).
// ---------------------------------------------------------------------------
#define PAD 40
#define MAT_EL (128 * PAD)
#define MAT_B (MAT_EL * 2)
#define STAGE_B (4 * MAT_B)
#define GEMM_SMEM (2 * STAGE_B)
#define NCHUNK (GK / 32)

__global__ __launch_bounds__(256) void tc_gemm_mma(
    const __nv_bfloat16* __restrict__ Ah, const __nv_bfloat16* __restrict__ Al,
    const __nv_bfloat16* __restrict__ Bh, const __nv_bfloat16* __restrict__ Bl,
    const float* __restrict__ bias, float* __restrict__ Co, int N)
{
    extern __shared__ char smem[];
    const uint32_t sb = smem_u32(smem);
    const int tid = threadIdx.x;
    const int wid = tid >> 5, lane = tid & 31;
    const int warp_m = wid >> 1, warp_n = wid & 1;
    const int m0 = blockIdx.y * 128, n0 = blockIdx.x * 128;

    const __nv_bfloat16* srcs[4] = {
        Ah + (size_t)m0 * GK, Al + (size_t)m0 * GK,
        Bh + (size_t)n0 * GK, Bl + (size_t)n0 * GK };

    auto prefetch = [&](int c, int stage) {
        const int k0 = c * 32;
        const uint32_t so = sb + stage * STAGE_B;
#pragma unroll
        for (int msel = 0; msel < 4; msel++) {
#pragma unroll
            for (int i = 0; i < 2; i++) {
                int idx = tid + i * 256;
                int r = idx >> 2, seg = idx & 3;
                uint32_t dst = so + msel * MAT_B + (uint32_t)(r * PAD + seg * 8) * 2;
                cp_async16(dst, srcs[msel] + (size_t)r * GK + k0 + seg * 8);
            }
        }
    };

    float acc[2][8][4];
#pragma unroll
    for (int a = 0; a < 2; a++)
#pragma unroll
        for (int b = 0; b < 8; b++)
#pragma unroll
            for (int c = 0; c < 4; c++) acc[a][b][c] = 0.f;

    prefetch(0, 0);
    cp_commit();

    const int a_row = (lane & 15);
    const int a_col8 = (lane >> 4) << 3;
    const int b_tile = lane >> 3;
    const int b_rin = lane & 7;
    const int b_nrow = ((b_tile >> 1) << 3) + b_rin;
    const int b_kcol = (b_tile & 1) << 3;

    for (int c = 0; c < NCHUNK; c++) {
        const int stage = c & 1;
        if (c + 1 < NCHUNK) { prefetch(c + 1, stage ^ 1); cp_commit(); }
        if (c + 1 < NCHUNK) cp_wait<1>(); else cp_wait<0>();
        __syncthreads();

        const uint32_t so = sb + stage * STAGE_B;
#pragma unroll
        for (int ks = 0; ks < 2; ks++) {
            uint32_t aH[2][4], aL[2][4], bH[4][4], bL[4][4];
#pragma unroll
            for (int mi = 0; mi < 2; mi++) {
                uint32_t off = (uint32_t)((warp_m * 32 + mi * 16 + a_row) * PAD
                                          + ks * 16 + a_col8) * 2;
                ldm_x4(aH[mi], so + 0 * MAT_B + off);
                ldm_x4(aL[mi], so + 1 * MAT_B + off);
            }
#pragma unroll
            for (int nj = 0; nj < 4; nj++) {
                uint32_t off = (uint32_t)((warp_n * 64 + nj * 16 + b_nrow) * PAD
                                          + ks * 16 + b_kcol) * 2;
                ldm_x4(bH[nj], so + 2 * MAT_B + off);
                ldm_x4(bL[nj], so + 3 * MAT_B + off);
            }
            // pass-major: 16 independent accumulators per pass (RAW dist 16).
            // Per-accumulator contribution order HH -> HL -> LH is unchanged
            // vs round 5, so the result is bit-identical.
#pragma unroll
            for (int mi = 0; mi < 2; mi++)
#pragma unroll
                for (int nj = 0; nj < 4; nj++) {
                    mma_bf16_v(acc[mi][nj * 2],     aH[mi], bH[nj][0], bH[nj][1]);
                    mma_bf16_v(acc[mi][nj * 2 + 1], aH[mi], bH[nj][2], bH[nj][3]);
                }
#pragma unroll
            for (int mi = 0; mi < 2; mi++)
#pragma unroll
                for (int nj = 0; nj < 4; nj++) {
                    mma_bf16_v(acc[mi][nj * 2],     aH[mi], bL[nj][0], bL[nj][1]);
                    mma_bf16_v(acc[mi][nj * 2 + 1], aH[mi], bL[nj][2], bL[nj][3]);
                }
#pragma unroll
            for (int mi = 0; mi < 2; mi++)
#pragma unroll
                for (int nj = 0; nj < 4; nj++) {
                    mma_bf16_v(acc[mi][nj * 2],     aL[mi], bH[nj][0], bH[nj][1]);
                    mma_bf16_v(acc[mi][nj * 2 + 1], aL[mi], bH[nj][2], bH[nj][3]);
                }
        }
        __syncthreads();
    }

    const int r_base = m0 + warp_m * 32 + (lane >> 2);
    const int c_base = n0 + warp_n * 64 + (lane & 3) * 2;
#pragma unroll
    for (int mi = 0; mi < 2; mi++) {
#pragma unroll
        for (int nj8 = 0; nj8 < 8; nj8++) {
            int col = c_base + nj8 * 8;
            float b0 = __ldg(bias + col), b1 = __ldg(bias + col + 1);
            int r0 = r_base + mi * 16;
            Co[(size_t)r0 * N + col]           = acc[mi][nj8][0] + b0;
            Co[(size_t)r0 * N + col + 1]       = acc[mi][nj8][1] + b1;
            Co[(size_t)(r0 + 8) * N + col]     = acc[mi][nj8][2] + b0;
            Co[(size_t)(r0 + 8) * N + col + 1] = acc[mi][nj8][3] + b1;
        }
    }
}

// ---------------------------------------------------------------------------
// Tensor-core causal flash attention (unchanged from round 7; 370 us).
// ---------------------------------------------------------------------------
#define PADA 72
#define KTB  9216  // one [64][72] bf16 tile

__global__ __launch_bounds__(256) void flash_mma_kernel(
    const float* __restrict__ qkv,
    __nv_bfloat16* __restrict__ yhi, __nv_bfloat16* __restrict__ ylo)
{
    __shared__ __align__(16) char smem[36864];
    const uint32_t sb = smem_u32(smem);
    const int tid = threadIdx.x;
    const int wid = tid >> 5, lane = tid & 31;
    const int bh = blockIdx.x, b = bh >> 4, h = bh & 15;
    const int qt = (T_ / 128 - 1) - blockIdx.y;  // long CTAs first
    const int q0 = qt * 128;
    const float* base = qkv + (size_t)b * T_ * C3;

    // ---- stage Q (scaled by 1/8) as hi/lo bf16 ----
    {
        const int r = tid >> 1;
        const int cb = (tid & 1) * 32;
        const float* qp = base + (size_t)(q0 + r) * C3 + h * D_ + cb;
#pragma unroll
        for (int i = 0; i < 8; i++) {
            float4 v = *(const float4*)(qp + i * 4);
            v.x *= 0.125f; v.y *= 0.125f; v.z *= 0.125f; v.w *= 0.125f;
            uint32_t h0, l0, h1, l1;
            split_pair(v.x, v.y, h0, l0);
            split_pair(v.z, v.w, h1, l1);
            uint32_t off = (uint32_t)(r * PADA + cb + i * 4) * 2;
            *(uint32_t*)(smem + off)             = h0;
            *(uint32_t*)(smem + off + 4)         = h1;
            *(uint32_t*)(smem + 18432 + off)     = l0;
            *(uint32_t*)(smem + 18432 + off + 4) = l1;
        }
    }
    __syncthreads();

    const int a_row = lane & 15;
    const int a_col8 = (lane >> 4) << 3;
    const int b_tile = lane >> 3;
    const int b_nrow = ((b_tile >> 1) << 3) + (lane & 7);
    const int b_kcol = (b_tile & 1) << 3;
    const int v_krow = ((b_tile & 1) << 3) + (lane & 7);
    const int v_ncol = (b_tile >> 1) << 3;

    uint32_t aQh[4][4], aQl[4][4];
#pragma unroll
    for (int ks = 0; ks < 4; ks++) {
        uint32_t off = (uint32_t)((wid * 16 + a_row) * PADA + ks * 16 + a_col8) * 2;
        ldm_x4(aQh[ks], sb + off);
        ldm_x4(aQl[ks], sb + 18432 + off);
    }

    float oacc[8][4];
#pragma unroll
    for (int i = 0; i < 8; i++)
#pragma unroll
        for (int j = 0; j < 4; j++) oacc[i][j] = 0.f;
    float mrow[2] = {-1e30f, -1e30f};
    float lrow[2] = {0.f, 0.f};

    const int ntiles = 2 * (qt + 1);
    for (int kt = 0; kt < ntiles; kt++) {
        const int k0 = kt * 64;
        __syncthreads();

        // ---- fill K hi/lo and V hi/lo, both [key][dim] (coalesced) ----
#pragma unroll
        for (int i = 0; i < 4; i++) {
            int ii = tid + i * 256;
            int kr = ii >> 4;
            int c4 = (ii & 15) * 4;
            const float* kp = base + (size_t)(k0 + kr) * C3 + C_ + h * D_ + c4;
            uint32_t off = (uint32_t)(kr * PADA + c4) * 2;

            float4 kv = *(const float4*)kp;
            uint32_t h0, l0, h1, l1;
            split_pair(kv.x, kv.y, h0, l0);
            split_pair(kv.z, kv.w, h1, l1);
            *(uint32_t*)(smem + off)           = h0;
            *(uint32_t*)(smem + off + 4)       = h1;
            *(uint32_t*)(smem + KTB + off)     = l0;
            *(uint32_t*)(smem + KTB + off + 4) = l1;

            float4 vv = *(const float4*)(kp + C_);
            split_pair(vv.x, vv.y, h0, l0);
            split_pair(vv.z, vv.w, h1, l1);
            *(uint32_t*)(smem + 2 * KTB + off)     = h0;
            *(uint32_t*)(smem + 2 * KTB + off + 4) = h1;
            *(uint32_t*)(smem + 3 * KTB + off)     = l0;
            *(uint32_t*)(smem + 3 * KTB + off + 4) = l1;
        }
        __syncthreads();

        // ---- S = Q @ K^T (3-pass) ----
        float sacc[8][4];
#pragma unroll
        for (int i = 0; i < 8; i++)
#pragma unroll
            for (int j = 0; j < 4; j++) sacc[i][j] = 0.f;
#pragma unroll
        for (int ks = 0; ks < 4; ks++) {
            uint32_t bH[4], bL[4];
#pragma unroll
            for (int nj = 0; nj < 4; nj++) {
                uint32_t off = (uint32_t)((nj * 16 + b_nrow) * PADA
                                          + ks * 16 + b_kcol) * 2;
                ldm_x4(bH, sb + off);
                ldm_x4(bL, sb + KTB + off);
                mma_bf16(sacc[nj * 2],     aQh[ks], bH[0], bH[1]);
                mma_bf16(sacc[nj * 2 + 1], aQh[ks], bH[2], bH[3]);
                mma_bf16(sacc[nj * 2],     aQh[ks], bL[0], bL[1]);
                mma_bf16(sacc[nj * 2 + 1], aQh[ks], bL[2], bL[3]);
                mma_bf16(sacc[nj * 2],     aQl[ks], bH[0], bH[1]);
                mma_bf16(sacc[nj * 2 + 1], aQl[ks], bH[2], bH[3]);
            }
        }

        // ---- causal mask (last two tiles only) ----
        if (k0 >= q0) {
            const int qg = q0 + wid * 16 + (lane >> 2);
            const int cg = k0 + (lane & 3) * 2;
#pragma unroll
            for (int nb = 0; nb < 8; nb++) {
                int col = cg + nb * 8;
                if (col > qg)          sacc[nb][0] = -1e30f;
                if (col + 1 > qg)      sacc[nb][1] = -1e30f;
                if (col > qg + 8)      sacc[nb][2] = -1e30f;
                if (col + 1 > qg + 8)  sacc[nb][3] = -1e30f;
            }
        }

        // ---- online softmax ----
        float mn0 = mrow[0], mn1 = mrow[1];
#pragma unroll
        for (int nb = 0; nb < 8; nb++) {
            mn0 = fmaxf(mn0, fmaxf(sacc[nb][0], sacc[nb][1]));
            mn1 = fmaxf(mn1, fmaxf(sacc[nb][2], sacc[nb][3]));
        }
        mn0 = fmaxf(mn0, __shfl_xor_sync(0xFFFFFFFF, mn0, 1));
        mn0 = fmaxf(mn0, __shfl_xor_sync(0xFFFFFFFF, mn0, 2));
        mn1 = fmaxf(mn1, __shfl_xor_sync(0xFFFFFFFF, mn1, 1));
        mn1 = fmaxf(mn1, __shfl_xor_sync(0xFFFFFFFF, mn1, 2));
        const float corr0 = __expf(mrow[0] - mn0);
        const float corr1 = __expf(mrow[1] - mn1);
        mrow[0] = mn0; mrow[1] = mn1;

        float ps0 = 0.f, ps1 = 0.f;
#pragma unroll
        for (int nb = 0; nb < 8; nb++) {
            sacc[nb][0] = __expf(sacc[nb][0] - mn0);
            sacc[nb][1] = __expf(sacc[nb][1] - mn0);
            sacc[nb][2] = __expf(sacc[nb][2] - mn1);
            sacc[nb][3] = __expf(sacc[nb][3] - mn1);
            ps0 += sacc[nb][0] + sacc[nb][1];
            ps1 += sacc[nb][2] + sacc[nb][3];
        }
        ps0 += __shfl_xor_sync(0xFFFFFFFF, ps0, 1);
        ps0 += __shfl_xor_sync(0xFFFFFFFF, ps0, 2);
        ps1 += __shfl_xor_sync(0xFFFFFFFF, ps1, 1);
        ps1 += __shfl_xor_sync(0xFFFFFFFF, ps1, 2);
        lrow[0] = lrow[0] * corr0 + ps0;
        lrow[1] = lrow[1] * corr1 + ps1;
#pragma unroll
        for (int nb = 0; nb < 8; nb++) {
            oacc[nb][0] *= corr0; oacc[nb][1] *= corr0;
            oacc[nb][2] *= corr1; oacc[nb][3] *= corr1;
        }

        // ---- O += P @ V (3-pass, V via ldmatrix.trans) ----
#pragma unroll
        for (int ks = 0; ks < 4; ks++) {
            uint32_t pH[4], pL[4];
            split_pair(sacc[2 * ks][0],     sacc[2 * ks][1],     pH[0], pL[0]);
            split_pair(sacc[2 * ks][2],     sacc[2 * ks][3],     pH[1], pL[1]);
            split_pair(sacc[2 * ks + 1][0], sacc[2 * ks + 1][1], pH[2], pL[2]);
            split_pair(sacc[2 * ks + 1][2], sacc[2 * ks + 1][3], pH[3], pL[3]);
#pragma unroll
            for (int nj = 0; nj < 4; nj++) {
                uint32_t bH[4], bL[4];
                uint32_t off = (uint32_t)((ks * 16 + v_krow) * PADA
                                          + nj * 16 + v_ncol) * 2;
                ldm_x4_trans(bH, sb + 2 * KTB + off);
                ldm_x4_trans(bL, sb + 3 * KTB + off);
                mma_bf16(oacc[nj * 2],     pH, bH[0], bH[1]);
                mma_bf16(oacc[nj * 2 + 1], pH, bH[2], bH[3]);
                mma_bf16(oacc[nj * 2],     pH, bL[0], bL[1]);
                mma_bf16(oacc[nj * 2 + 1], pH, bL[2], bL[3]);
                mma_bf16(oacc[nj * 2],     pL, bH[0], bH[1]);
                mma_bf16(oacc[nj * 2 + 1], pL, bH[2], bH[3]);
            }
        }
    }

    // ---- normalize and write y as bf16 hi/lo (fused split) ----
    const float inv0 = 1.f / lrow[0];
    const float inv1 = 1.f / lrow[1];
    const int rg = q0 + wid * 16 + (lane >> 2);
    const size_t e0 = ((size_t)b * T_ + rg) * C_ + h * D_ + (lane & 3) * 2;
#pragma unroll
    for (int nb = 0; nb < 8; nb++) {
        uint32_t h0, l0, h1, l1;
        split_pair(oacc[nb][0] * inv0, oacc[nb][1] * inv0, h0, l0);
        split_pair(oacc[nb][2] * inv1, oacc[nb][3] * inv1, h1, l1);
        *(uint32_t*)(yhi + e0 + nb * 8)          = h0;
        *(uint32_t*)(ylo + e0 + nb * 8)          = l0;
        *(uint32_t*)(yhi + e0 + 8 * C_ + nb * 8) = h1;
        *(uint32_t*)(ylo + e0 + 8 * C_ + nb * 8) = l1;
    }
}

// ---------------------------------------------------------------------------
extern "C" void kernel_launch(void* const* d_in, const int* in_sizes, int n_in,
                              void* d_out, int out_size)
{
    const float* x      = (const float*)d_in[0];
    const float* W_attn = (const float*)d_in[1];
    const float* b_attn = (const float*)d_in[2];
    const float* W_proj = (const float*)d_in[3];
    const float* b_proj = (const float*)d_in[4];
    float* out = (float*)d_out;

    float *qkv_p;
    __nv_bfloat16 *xhi, *xlo, *yhi, *ylo, *wahi, *walo, *wphi, *wplo;
    cudaGetSymbolAddress((void**)&qkv_p, g_qkv);
    cudaGetSymbolAddress((void**)&xhi, g_xhi);
    cudaGetSymbolAddress((void**)&xlo, g_xlo);
    cudaGetSymbolAddress((void**)&yhi, g_yhi);
    cudaGetSymbolAddress((void**)&ylo, g_ylo);
    cudaGetSymbolAddress((void**)&wahi, g_wahi);
    cudaGetSymbolAddress((void**)&walo, g_walo);
    cudaGetSymbolAddress((void**)&wphi, g_wphi);
    cudaGetSymbolAddress((void**)&wplo, g_wplo);

    cudaFuncSetAttribute(tc_gemm_mma, cudaFuncAttributeMaxDynamicSharedMemorySize,
                         GEMM_SMEM);

    const int NTOK_EL = M_TOK * C_;

    // 1) split x -> bf16 hi/lo
    split_kernel<<<NTOK_EL / 8 / 256, 256>>>(x, xhi, xlo, NTOK_EL);
    // 2) transpose+split weights
    transpose_split<<<dim3(C3 / 32, C_ / 32), dim3(32, 8)>>>(W_attn, wahi, walo, C_, C3);
    transpose_split<<<dim3(C_ / 32, C_ / 32), dim3(32, 8)>>>(W_proj, wphi, wplo, C_, C_);
    // 3) QKV GEMM (tensor cores)
    tc_gemm_mma<<<dim3(C3 / 128, M_TOK / 128), 256, GEMM_SMEM>>>(
        xhi, xlo, wahi, walo, b_attn, qkv_p, C3);
    // 4) causal flash attention (tensor cores), y split fused in epilogue
    flash_mma_kernel<<<dim3(B_ * H_, T_ / 128), 256>>>(qkv_p, yhi, ylo);
    // 5) proj GEMM (tensor cores) -> d_out
    tc_gemm_mma<<<dim3(C_ / 128, M_TOK / 128), 256, GEMM_SMEM>>>(
        yhi, ylo, wphi, wplo, b_proj, out, C_);
}

// round 9
// speedup vs baseline: 1.2652x; 1.0393x over previous
#include <cuda_runtime.h>
#include <cuda_bf16.h>
#include <cstdint>
#include <cstddef>

// Problem constants
#define B_  4
#define T_  2048
#define C_  1024
#define H_  16
#define D_  64
#define M_TOK (B_ * T_)      // 8192
#define C3 (3 * C_)          // 3072
#define GK 1024              // K of both GEMMs

// ---------------------------------------------------------------------------
// Scratch (device globals; allocation in kernel_launch is forbidden)
// ---------------------------------------------------------------------------
__device__ __nv_bfloat16 g_qkvh[(size_t)M_TOK * C3]; // qkv hi (from GEMM epi)
__device__ __nv_bfloat16 g_qkvl[(size_t)M_TOK * C3]; // qkv lo
__device__ __nv_bfloat16 g_xhi[(size_t)M_TOK * C_];
__device__ __nv_bfloat16 g_xlo[(size_t)M_TOK * C_];
__device__ __nv_bfloat16 g_yhi[(size_t)M_TOK * C_];
__device__ __nv_bfloat16 g_ylo[(size_t)M_TOK * C_];
__device__ __nv_bfloat16 g_wahi[(size_t)C3 * C_];  // W_attn^T [3C][C]
__device__ __nv_bfloat16 g_walo[(size_t)C3 * C_];
__device__ __nv_bfloat16 g_wphi[(size_t)C_ * C_];  // W_proj^T [C][C]
__device__ __nv_bfloat16 g_wplo[(size_t)C_ * C_];

// ---------------------------------------------------------------------------
// PTX helpers
// ---------------------------------------------------------------------------
__device__ __forceinline__ uint32_t smem_u32(const void* p) {
    uint32_t a;
    asm("{ .reg .u64 t; cvta.to.shared.u64 t, %1; cvt.u32.u64 %0, t; }"
        : "=r"(a) : "l"(p));
    return a;
}
__device__ __forceinline__ void cp_async16(uint32_t dst, const void* src) {
    asm volatile("cp.async.cg.shared.global [%0], [%1], 16;"
                 :: "r"(dst), "l"(src) : "memory");
}
__device__ __forceinline__ void cp_commit() {
    asm volatile("cp.async.commit_group;" ::: "memory");
}
template <int N>
__device__ __forceinline__ void cp_wait() {
    asm volatile("cp.async.wait_group %0;" :: "n"(N) : "memory");
}
__device__ __forceinline__ void ldm_x4(uint32_t* r, uint32_t addr) {
    asm volatile("ldmatrix.sync.aligned.m8n8.x4.shared.b16 {%0,%1,%2,%3}, [%4];"
                 : "=r"(r[0]), "=r"(r[1]), "=r"(r[2]), "=r"(r[3]) : "r"(addr));
}
__device__ __forceinline__ void ldm_x4_trans(uint32_t* r, uint32_t addr) {
    asm volatile("ldmatrix.sync.aligned.m8n8.x4.trans.shared.b16 {%0,%1,%2,%3}, [%4];"
                 : "=r"(r[0]), "=r"(r[1]), "=r"(r[2]), "=r"(r[3]) : "r"(addr));
}
__device__ __forceinline__ void mma_bf16_v(float* d, const uint32_t* a,
                                           uint32_t b0, uint32_t b1) {
    asm volatile(
        "mma.sync.aligned.m16n8k16.row.col.f32.bf16.bf16.f32 "
        "{%0,%1,%2,%3}, {%4,%5,%6,%7}, {%8,%9}, {%0,%1,%2,%3};"
        : "+f"(d[0]), "+f"(d[1]), "+f"(d[2]), "+f"(d[3])
        : "r"(a[0]), "r"(a[1]), "r"(a[2]), "r"(a[3]), "r"(b0), "r"(b1));
}
__device__ __forceinline__ void mma_bf16(float* d, const uint32_t* a,
                                         uint32_t b0, uint32_t b1) {
    asm("mma.sync.aligned.m16n8k16.row.col.f32.bf16.bf16.f32 "
        "{%0,%1,%2,%3}, {%4,%5,%6,%7}, {%8,%9}, {%0,%1,%2,%3};"
        : "+f"(d[0]), "+f"(d[1]), "+f"(d[2]), "+f"(d[3])
        : "r"(a[0]), "r"(a[1]), "r"(a[2]), "r"(a[3]), "r"(b0), "r"(b1));
}
__device__ __forceinline__ uint32_t b2u(__nv_bfloat162 v) {
    return *reinterpret_cast<uint32_t*>(&v);
}
__device__ __forceinline__ void split_pair(float x, float y,
                                           uint32_t& hi, uint32_t& lo) {
    __nv_bfloat162 h = __float22bfloat162_rn(make_float2(x, y));
    float2 hf = __bfloat1622float2(h);
    __nv_bfloat162 l = __float22bfloat162_rn(make_float2(x - hf.x, y - hf.y));
    hi = b2u(h); lo = b2u(l);
}

// ---------------------------------------------------------------------------
// Conversion kernels
// ---------------------------------------------------------------------------
__global__ void split_kernel(const float* __restrict__ in,
                             __nv_bfloat16* __restrict__ hi,
                             __nv_bfloat16* __restrict__ lo, int n)
{
    int i = (blockIdx.x * blockDim.x + threadIdx.x) * 8;
    if (i >= n) return;
    float4 a = *(const float4*)(in + i);
    float4 b = *(const float4*)(in + i + 4);
    float v[8] = {a.x, a.y, a.z, a.w, b.x, b.y, b.z, b.w};
    __nv_bfloat16 h[8], l[8];
#pragma unroll
    for (int j = 0; j < 8; j++) {
        h[j] = __float2bfloat16(v[j]);
        l[j] = __float2bfloat16(v[j] - __bfloat162float(h[j]));
    }
    *(uint4*)(hi + i) = *(uint4*)h;
    *(uint4*)(lo + i) = *(uint4*)l;
}

// W [K][N] row-major -> Wt hi/lo [N][K]
__global__ void transpose_split(const float* __restrict__ W,
                                __nv_bfloat16* __restrict__ Thi,
                                __nv_bfloat16* __restrict__ Tlo,
                                int K, int N)
{
    __shared__ float tile[32][33];
    int k0 = blockIdx.y * 32, n0 = blockIdx.x * 32;
    int tx = threadIdx.x, ty = threadIdx.y;
#pragma unroll
    for (int i = ty; i < 32; i += 8)
        tile[i][tx] = W[(size_t)(k0 + i) * N + n0 + tx];
    __syncthreads();
#pragma unroll
    for (int i = ty; i < 32; i += 8) {
        float v = tile[tx][i];
        __nv_bfloat16 h = __float2bfloat16(v);
        float r = v - __bfloat162float(h);
        Thi[(size_t)(n0 + i) * K + k0 + tx] = h;
        Tlo[(size_t)(n0 + i) * K + k0 + tx] = __float2bfloat16(r);
    }
}

// ---------------------------------------------------------------------------
// mma.sync bf16 split GEMM (round-5 mainloop). Epilogue either writes fp32
// (proj) or bf16 hi/lo split (QKV -> attention consumes bf16 directly).
// ---------------------------------------------------------------------------
#define PAD 40
#define MAT_EL (128 * PAD)
#define MAT_B (MAT_EL * 2)
#define STAGE_B (4 * MAT_B)
#define GEMM_SMEM (2 * STAGE_B)
#define NCHUNK (GK / 32)

__global__ __launch_bounds__(256) void tc_gemm_mma(
    const __nv_bfloat16* __restrict__ Ah, const __nv_bfloat16* __restrict__ Al,
    const __nv_bfloat16* __restrict__ Bh, const __nv_bfloat16* __restrict__ Bl,
    const float* __restrict__ bias, float* __restrict__ Co,
    __nv_bfloat16* __restrict__ Chi, __nv_bfloat16* __restrict__ Clo,
    int N, int split_out)
{
    extern __shared__ char smem[];
    const uint32_t sb = smem_u32(smem);
    const int tid = threadIdx.x;
    const int wid = tid >> 5, lane = tid & 31;
    const int warp_m = wid >> 1, warp_n = wid & 1;
    const int m0 = blockIdx.y * 128, n0 = blockIdx.x * 128;

    const __nv_bfloat16* srcs[4] = {
        Ah + (size_t)m0 * GK, Al + (size_t)m0 * GK,
        Bh + (size_t)n0 * GK, Bl + (size_t)n0 * GK };

    auto prefetch = [&](int c, int stage) {
        const int k0 = c * 32;
        const uint32_t so = sb + stage * STAGE_B;
#pragma unroll
        for (int msel = 0; msel < 4; msel++) {
#pragma unroll
            for (int i = 0; i < 2; i++) {
                int idx = tid + i * 256;
                int r = idx >> 2, seg = idx & 3;
                uint32_t dst = so + msel * MAT_B + (uint32_t)(r * PAD + seg * 8) * 2;
                cp_async16(dst, srcs[msel] + (size_t)r * GK + k0 + seg * 8);
            }
        }
    };

    float acc[2][8][4];
#pragma unroll
    for (int a = 0; a < 2; a++)
#pragma unroll
        for (int b = 0; b < 8; b++)
#pragma unroll
            for (int c = 0; c < 4; c++) acc[a][b][c] = 0.f;

    prefetch(0, 0);
    cp_commit();

    const int a_row = (lane & 15);
    const int a_col8 = (lane >> 4) << 3;
    const int b_tile = lane >> 3;
    const int b_rin = lane & 7;
    const int b_nrow = ((b_tile >> 1) << 3) + b_rin;
    const int b_kcol = (b_tile & 1) << 3;

    for (int c = 0; c < NCHUNK; c++) {
        const int stage = c & 1;
        if (c + 1 < NCHUNK) { prefetch(c + 1, stage ^ 1); cp_commit(); }
        if (c + 1 < NCHUNK) cp_wait<1>(); else cp_wait<0>();
        __syncthreads();

        const uint32_t so = sb + stage * STAGE_B;
#pragma unroll
        for (int ks = 0; ks < 2; ks++) {
            uint32_t aH[2][4], aL[2][4], bH[4][4], bL[4][4];
#pragma unroll
            for (int mi = 0; mi < 2; mi++) {
                uint32_t off = (uint32_t)((warp_m * 32 + mi * 16 + a_row) * PAD
                                          + ks * 16 + a_col8) * 2;
                ldm_x4(aH[mi], so + 0 * MAT_B + off);
                ldm_x4(aL[mi], so + 1 * MAT_B + off);
            }
#pragma unroll
            for (int nj = 0; nj < 4; nj++) {
                uint32_t off = (uint32_t)((warp_n * 64 + nj * 16 + b_nrow) * PAD
                                          + ks * 16 + b_kcol) * 2;
                ldm_x4(bH[nj], so + 2 * MAT_B + off);
                ldm_x4(bL[nj], so + 3 * MAT_B + off);
            }
#pragma unroll
            for (int mi = 0; mi < 2; mi++)
#pragma unroll
                for (int nj = 0; nj < 4; nj++) {
                    mma_bf16_v(acc[mi][nj * 2],     aH[mi], bH[nj][0], bH[nj][1]);
                    mma_bf16_v(acc[mi][nj * 2 + 1], aH[mi], bH[nj][2], bH[nj][3]);
                    mma_bf16_v(acc[mi][nj * 2],     aH[mi], bL[nj][0], bL[nj][1]);
                    mma_bf16_v(acc[mi][nj * 2 + 1], aH[mi], bL[nj][2], bL[nj][3]);
                    mma_bf16_v(acc[mi][nj * 2],     aL[mi], bH[nj][0], bH[nj][1]);
                    mma_bf16_v(acc[mi][nj * 2 + 1], aL[mi], bH[nj][2], bH[nj][3]);
                }
        }
        __syncthreads();
    }

    const int r_base = m0 + warp_m * 32 + (lane >> 2);
    const int c_base = n0 + warp_n * 64 + (lane & 3) * 2;
    if (split_out) {
#pragma unroll
        for (int mi = 0; mi < 2; mi++) {
#pragma unroll
            for (int nj8 = 0; nj8 < 8; nj8++) {
                int col = c_base + nj8 * 8;
                float b0 = __ldg(bias + col), b1 = __ldg(bias + col + 1);
                int r0 = r_base + mi * 16;
                uint32_t hh, ll;
                split_pair(acc[mi][nj8][0] + b0, acc[mi][nj8][1] + b1, hh, ll);
                *(uint32_t*)(Chi + (size_t)r0 * N + col) = hh;
                *(uint32_t*)(Clo + (size_t)r0 * N + col) = ll;
                split_pair(acc[mi][nj8][2] + b0, acc[mi][nj8][3] + b1, hh, ll);
                *(uint32_t*)(Chi + (size_t)(r0 + 8) * N + col) = hh;
                *(uint32_t*)(Clo + (size_t)(r0 + 8) * N + col) = ll;
            }
        }
    } else {
#pragma unroll
        for (int mi = 0; mi < 2; mi++) {
#pragma unroll
            for (int nj8 = 0; nj8 < 8; nj8++) {
                int col = c_base + nj8 * 8;
                float b0 = __ldg(bias + col), b1 = __ldg(bias + col + 1);
                int r0 = r_base + mi * 16;
                Co[(size_t)r0 * N + col]           = acc[mi][nj8][0] + b0;
                Co[(size_t)r0 * N + col + 1]       = acc[mi][nj8][1] + b1;
                Co[(size_t)(r0 + 8) * N + col]     = acc[mi][nj8][2] + b0;
                Co[(size_t)(r0 + 8) * N + col + 1] = acc[mi][nj8][3] + b1;
            }
        }
    }
}

// ---------------------------------------------------------------------------
// Tensor-core causal flash attention, cp.async staging from pre-split bf16
// qkv, double-buffered KV tiles (DMA of tile kt+1 overlaps MMAs of tile kt).
// smem: Qh[128][72]@0, Ql@18432, then 2 KV stages of
//       {Kh,Kl,Vh,Vl}[64][72] (9216 each, 36864/stage).
// ---------------------------------------------------------------------------
#define PADA 72
#define KTB  9216
#define QB   18432
#define KVS  36864
#define KVBASE (2 * QB)
#define FLASH_SMEM (KVBASE + 2 * KVS)   // 110592

__global__ __launch_bounds__(256) void flash_mma_kernel(
    const __nv_bfloat16* __restrict__ qkvh,
    const __nv_bfloat16* __restrict__ qkvl,
    __nv_bfloat16* __restrict__ yhi, __nv_bfloat16* __restrict__ ylo)
{
    extern __shared__ __align__(16) char smem[];
    const uint32_t sb = smem_u32(smem);
    const int tid = threadIdx.x;
    const int wid = tid >> 5, lane = tid & 31;
    const int bh = blockIdx.x, b = bh >> 4, h = bh & 15;
    const int qt = (T_ / 128 - 1) - blockIdx.y;  // long CTAs first
    const int q0 = qt * 128;
    const size_t rowbase = (size_t)b * T_ * C3;

    auto fillKV = [&](int kt, int s) {
        const int k0 = kt * 64;
        const uint32_t so = sb + KVBASE + s * KVS;
#pragma unroll
        for (int i = 0; i < 8; i++) {
            int idx = tid + i * 256;
            int mat = idx >> 9;            // 0=Kh 1=Kl 2=Vh 3=Vl
            int rem = idx & 511;
            int r = rem >> 3, seg = rem & 7;
            const __nv_bfloat16* src =
                ((mat & 1) ? qkvl : qkvh) + rowbase + (size_t)(k0 + r) * C3
                + ((mat >> 1) ? 2 * C_ : C_) + h * D_ + seg * 8;
            cp_async16(so + (uint32_t)(mat * KTB + r * 144 + seg * 16), src);
        }
    };

    // ---- stage Q (unscaled hi/lo; 1/8 applied to scores post-MMA) ----
    {
#pragma unroll
        for (int i = 0; i < 8; i++) {
            int idx = tid + i * 256;       // 0..2047
            int mat = idx >> 10;           // 0=hi 1=lo
            int rem = idx & 1023;
            int r = rem >> 3, seg = rem & 7;
            const __nv_bfloat16* src =
                (mat ? qkvl : qkvh) + rowbase + (size_t)(q0 + r) * C3
                + h * D_ + seg * 8;
            cp_async16(sb + (uint32_t)(mat * QB + r * 144 + seg * 16), src);
        }
    }
    cp_commit();
    fillKV(0, 0);
    cp_commit();

    const int a_row = lane & 15;
    const int a_col8 = (lane >> 4) << 3;
    const int b_tile = lane >> 3;
    const int b_nrow = ((b_tile >> 1) << 3) + (lane & 7);
    const int b_kcol = (b_tile & 1) << 3;
    const int v_krow = ((b_tile & 1) << 3) + (lane & 7);
    const int v_ncol = (b_tile >> 1) << 3;

    cp_wait<1>();      // Q group done (KV0 may still be in flight)
    __syncthreads();

    uint32_t aQh[4][4], aQl[4][4];
#pragma unroll
    for (int ks = 0; ks < 4; ks++) {
        uint32_t off = (uint32_t)((wid * 16 + a_row) * PADA + ks * 16 + a_col8) * 2;
        ldm_x4(aQh[ks], sb + off);
        ldm_x4(aQl[ks], sb + QB + off);
    }

    float oacc[8][4];
#pragma unroll
    for (int i = 0; i < 8; i++)
#pragma unroll
        for (int j = 0; j < 4; j++) oacc[i][j] = 0.f;
    float mrow[2] = {-1e30f, -1e30f};
    float lrow[2] = {0.f, 0.f};

    const int ntiles = 2 * (qt + 1);
    for (int kt = 0; kt < ntiles; kt++) {
        const int s = kt & 1;
        const int k0 = kt * 64;
        __syncthreads();   // all warps done reading stage s^1 (tile kt-1)
        if (kt + 1 < ntiles) { fillKV(kt + 1, s ^ 1); cp_commit(); }
        if (kt + 1 < ntiles) cp_wait<1>(); else cp_wait<0>();
        __syncthreads();   // stage s (tile kt) visible to all

        const uint32_t kvso = sb + KVBASE + s * KVS;

        // ---- S = Q @ K^T (3-pass) ----
        float sacc[8][4];
#pragma unroll
        for (int i = 0; i < 8; i++)
#pragma unroll
            for (int j = 0; j < 4; j++) sacc[i][j] = 0.f;
#pragma unroll
        for (int ks = 0; ks < 4; ks++) {
            uint32_t bH[4], bL[4];
#pragma unroll
            for (int nj = 0; nj < 4; nj++) {
                uint32_t off = (uint32_t)((nj * 16 + b_nrow) * PADA
                                          + ks * 16 + b_kcol) * 2;
                ldm_x4(bH, kvso + off);
                ldm_x4(bL, kvso + KTB + off);
                mma_bf16(sacc[nj * 2],     aQh[ks], bH[0], bH[1]);
                mma_bf16(sacc[nj * 2 + 1], aQh[ks], bH[2], bH[3]);
                mma_bf16(sacc[nj * 2],     aQh[ks], bL[0], bL[1]);
                mma_bf16(sacc[nj * 2 + 1], aQh[ks], bL[2], bL[3]);
                mma_bf16(sacc[nj * 2],     aQl[ks], bH[0], bH[1]);
                mma_bf16(sacc[nj * 2 + 1], aQl[ks], bH[2], bH[3]);
            }
        }
        // apply 1/sqrt(D) = 1/8 (exact pow2; commutes with the bf16 split)
#pragma unroll
        for (int nb = 0; nb < 8; nb++) {
            sacc[nb][0] *= 0.125f; sacc[nb][1] *= 0.125f;
            sacc[nb][2] *= 0.125f; sacc[nb][3] *= 0.125f;
        }

        // ---- causal mask (last two tiles only) ----
        if (k0 >= q0) {
            const int qg = q0 + wid * 16 + (lane >> 2);
            const int cg = k0 + (lane & 3) * 2;
#pragma unroll
            for (int nb = 0; nb < 8; nb++) {
                int col = cg + nb * 8;
                if (col > qg)          sacc[nb][0] = -1e30f;
                if (col + 1 > qg)      sacc[nb][1] = -1e30f;
                if (col > qg + 8)      sacc[nb][2] = -1e30f;
                if (col + 1 > qg + 8)  sacc[nb][3] = -1e30f;
            }
        }

        // ---- online softmax ----
        float mn0 = mrow[0], mn1 = mrow[1];
#pragma unroll
        for (int nb = 0; nb < 8; nb++) {
            mn0 = fmaxf(mn0, fmaxf(sacc[nb][0], sacc[nb][1]));
            mn1 = fmaxf(mn1, fmaxf(sacc[nb][2], sacc[nb][3]));
        }
        mn0 = fmaxf(mn0, __shfl_xor_sync(0xFFFFFFFF, mn0, 1));
        mn0 = fmaxf(mn0, __shfl_xor_sync(0xFFFFFFFF, mn0, 2));
        mn1 = fmaxf(mn1, __shfl_xor_sync(0xFFFFFFFF, mn1, 1));
        mn1 = fmaxf(mn1, __shfl_xor_sync(0xFFFFFFFF, mn1, 2));
        const float corr0 = __expf(mrow[0] - mn0);
        const float corr1 = __expf(mrow[1] - mn1);
        mrow[0] = mn0; mrow[1] = mn1;

        float ps0 = 0.f, ps1 = 0.f;
#pragma unroll
        for (int nb = 0; nb < 8; nb++) {
            sacc[nb][0] = __expf(sacc[nb][0] - mn0);
            sacc[nb][1] = __expf(sacc[nb][1] - mn0);
            sacc[nb][2] = __expf(sacc[nb][2] - mn1);
            sacc[nb][3] = __expf(sacc[nb][3] - mn1);
            ps0 += sacc[nb][0] + sacc[nb][1];
            ps1 += sacc[nb][2] + sacc[nb][3];
        }
        ps0 += __shfl_xor_sync(0xFFFFFFFF, ps0, 1);
        ps0 += __shfl_xor_sync(0xFFFFFFFF, ps0, 2);
        ps1 += __shfl_xor_sync(0xFFFFFFFF, ps1, 1);
        ps1 += __shfl_xor_sync(0xFFFFFFFF, ps1, 2);
        lrow[0] = lrow[0] * corr0 + ps0;
        lrow[1] = lrow[1] * corr1 + ps1;
#pragma unroll
        for (int nb = 0; nb < 8; nb++) {
            oacc[nb][0] *= corr0; oacc[nb][1] *= corr0;
            oacc[nb][2] *= corr1; oacc[nb][3] *= corr1;
        }

        // ---- O += P @ V (3-pass, V via ldmatrix.trans) ----
#pragma unroll
        for (int ks = 0; ks < 4; ks++) {
            uint32_t pH[4], pL[4];
            split_pair(sacc[2 * ks][0],     sacc[2 * ks][1],     pH[0], pL[0]);
            split_pair(sacc[2 * ks][2],     sacc[2 * ks][3],     pH[1], pL[1]);
            split_pair(sacc[2 * ks + 1][0], sacc[2 * ks + 1][1], pH[2], pL[2]);
            split_pair(sacc[2 * ks + 1][2], sacc[2 * ks + 1][3], pH[3], pL[3]);
#pragma unroll
            for (int nj = 0; nj < 4; nj++) {
                uint32_t bH[4], bL[4];
                uint32_t off = (uint32_t)((ks * 16 + v_krow) * PADA
                                          + nj * 16 + v_ncol) * 2;
                ldm_x4_trans(bH, kvso + 2 * KTB + off);
                ldm_x4_trans(bL, kvso + 3 * KTB + off);
                mma_bf16(oacc[nj * 2],     pH, bH[0], bH[1]);
                mma_bf16(oacc[nj * 2 + 1], pH, bH[2], bH[3]);
                mma_bf16(oacc[nj * 2],     pH, bL[0], bL[1]);
                mma_bf16(oacc[nj * 2 + 1], pH, bL[2], bL[3]);
                mma_bf16(oacc[nj * 2],     pL, bH[0], bH[1]);
                mma_bf16(oacc[nj * 2 + 1], pL, bH[2], bH[3]);
            }
        }
    }

    // ---- normalize and write y as bf16 hi/lo (fused split) ----
    const float inv0 = 1.f / lrow[0];
    const float inv1 = 1.f / lrow[1];
    const int rg = q0 + wid * 16 + (lane >> 2);
    const size_t e0 = ((size_t)b * T_ + rg) * C_ + h * D_ + (lane & 3) * 2;
#pragma unroll
    for (int nb = 0; nb < 8; nb++) {
        uint32_t h0, l0, h1, l1;
        split_pair(oacc[nb][0] * inv0, oacc[nb][1] * inv0, h0, l0);
        split_pair(oacc[nb][2] * inv1, oacc[nb][3] * inv1, h1, l1);
        *(uint32_t*)(yhi + e0 + nb * 8)          = h0;
        *(uint32_t*)(ylo + e0 + nb * 8)          = l0;
        *(uint32_t*)(yhi + e0 + 8 * C_ + nb * 8) = h1;
        *(uint32_t*)(ylo + e0 + 8 * C_ + nb * 8) = l1;
    }
}

// ---------------------------------------------------------------------------
extern "C" void kernel_launch(void* const* d_in, const int* in_sizes, int n_in,
                              void* d_out, int out_size)
{
    const float* x      = (const float*)d_in[0];
    const float* W_attn = (const float*)d_in[1];
    const float* b_attn = (const float*)d_in[2];
    const float* W_proj = (const float*)d_in[3];
    const float* b_proj = (const float*)d_in[4];
    float* out = (float*)d_out;

    __nv_bfloat16 *qkvh, *qkvl, *xhi, *xlo, *yhi, *ylo, *wahi, *walo, *wphi, *wplo;
    cudaGetSymbolAddress((void**)&qkvh, g_qkvh);
    cudaGetSymbolAddress((void**)&qkvl, g_qkvl);
    cudaGetSymbolAddress((void**)&xhi, g_xhi);
    cudaGetSymbolAddress((void**)&xlo, g_xlo);
    cudaGetSymbolAddress((void**)&yhi, g_yhi);
    cudaGetSymbolAddress((void**)&ylo, g_ylo);
    cudaGetSymbolAddress((void**)&wahi, g_wahi);
    cudaGetSymbolAddress((void**)&walo, g_walo);
    cudaGetSymbolAddress((void**)&wphi, g_wphi);
    cudaGetSymbolAddress((void**)&wplo, g_wplo);

    cudaFuncSetAttribute(tc_gemm_mma, cudaFuncAttributeMaxDynamicSharedMemorySize,
                         GEMM_SMEM);
    cudaFuncSetAttribute(flash_mma_kernel,
                         cudaFuncAttributeMaxDynamicSharedMemorySize, FLASH_SMEM);

    const int NTOK_EL = M_TOK * C_;

    // 1) split x -> bf16 hi/lo
    split_kernel<<<NTOK_EL / 8 / 256, 256>>>(x, xhi, xlo, NTOK_EL);
    // 2) transpose+split weights
    transpose_split<<<dim3(C3 / 32, C_ / 32), dim3(32, 8)>>>(W_attn, wahi, walo, C_, C3);
    transpose_split<<<dim3(C_ / 32, C_ / 32), dim3(32, 8)>>>(W_proj, wphi, wplo, C_, C_);
    // 3) QKV GEMM -> qkv bf16 hi/lo (split fused in epilogue)
    tc_gemm_mma<<<dim3(C3 / 128, M_TOK / 128), 256, GEMM_SMEM>>>(
        xhi, xlo, wahi, walo, b_attn, nullptr, qkvh, qkvl, C3, 1);
    // 4) causal flash attention (cp.async staging, double-buffered KV)
    flash_mma_kernel<<<dim3(B_ * H_, T_ / 128), 256, FLASH_SMEM>>>(
        qkvh, qkvl, yhi, ylo);
    // 5) proj GEMM -> d_out (fp32)
    tc_gemm_mma<<<dim3(C_ / 128, M_TOK / 128), 256, GEMM_SMEM>>>(
        yhi, ylo, wphi, wplo, b_proj, out, nullptr, nullptr, C_, 0);
}

// round 10
// speedup vs baseline: 1.2752x; 1.0079x over previous
#include <cuda_runtime.h>
#include <cuda_bf16.h>
#include <cstdint>
#include <cstddef>

// Problem constants
#define B_  4
#define T_  2048
#define C_  1024
#define H_  16
#define D_  64
#define M_TOK (B_ * T_)      // 8192
#define C3 (3 * C_)          // 3072
#define GK 1024              // K of both GEMMs

// ---------------------------------------------------------------------------
// Scratch (device globals; allocation in kernel_launch is forbidden)
// ---------------------------------------------------------------------------
__device__ __nv_bfloat16 g_qkvh[(size_t)M_TOK * C3]; // qkv hi (from GEMM epi)
__device__ __nv_bfloat16 g_qkvl[(size_t)M_TOK * C3]; // qkv lo
__device__ __nv_bfloat16 g_xhi[(size_t)M_TOK * C_];
__device__ __nv_bfloat16 g_xlo[(size_t)M_TOK * C_];
__device__ __nv_bfloat16 g_yhi[(size_t)M_TOK * C_];
__device__ __nv_bfloat16 g_ylo[(size_t)M_TOK * C_];
__device__ __nv_bfloat16 g_wahi[(size_t)C3 * C_];  // W_attn^T [3C][C]
__device__ __nv_bfloat16 g_walo[(size_t)C3 * C_];
__device__ __nv_bfloat16 g_wphi[(size_t)C_ * C_];  // W_proj^T [C][C]
__device__ __nv_bfloat16 g_wplo[(size_t)C_ * C_];

// ---------------------------------------------------------------------------
// PTX helpers
// ---------------------------------------------------------------------------
__device__ __forceinline__ uint32_t smem_u32(const void* p) {
    uint32_t a;
    asm("{ .reg .u64 t; cvta.to.shared.u64 t, %1; cvt.u32.u64 %0, t; }"
        : "=r"(a) : "l"(p));
    return a;
}
__device__ __forceinline__ void cp_async16(uint32_t dst, const void* src) {
    asm volatile("cp.async.cg.shared.global [%0], [%1], 16;"
                 :: "r"(dst), "l"(src) : "memory");
}
__device__ __forceinline__ void cp_commit() {
    asm volatile("cp.async.commit_group;" ::: "memory");
}
template <int N>
__device__ __forceinline__ void cp_wait() {
    asm volatile("cp.async.wait_group %0;" :: "n"(N) : "memory");
}
__device__ __forceinline__ void ldm_x4(uint32_t* r, uint32_t addr) {
    asm volatile("ldmatrix.sync.aligned.m8n8.x4.shared.b16 {%0,%1,%2,%3}, [%4];"
                 : "=r"(r[0]), "=r"(r[1]), "=r"(r[2]), "=r"(r[3]) : "r"(addr));
}
__device__ __forceinline__ void ldm_x4_trans(uint32_t* r, uint32_t addr) {
    asm volatile("ldmatrix.sync.aligned.m8n8.x4.trans.shared.b16 {%0,%1,%2,%3}, [%4];"
                 : "=r"(r[0]), "=r"(r[1]), "=r"(r[2]), "=r"(r[3]) : "r"(addr));
}
__device__ __forceinline__ void mma_bf16_v(float* d, const uint32_t* a,
                                           uint32_t b0, uint32_t b1) {
    asm volatile(
        "mma.sync.aligned.m16n8k16.row.col.f32.bf16.bf16.f32 "
        "{%0,%1,%2,%3}, {%4,%5,%6,%7}, {%8,%9}, {%0,%1,%2,%3};"
        : "+f"(d[0]), "+f"(d[1]), "+f"(d[2]), "+f"(d[3])
        : "r"(a[0]), "r"(a[1]), "r"(a[2]), "r"(a[3]), "r"(b0), "r"(b1));
}
__device__ __forceinline__ void mma_bf16(float* d, const uint32_t* a,
                                         uint32_t b0, uint32_t b1) {
    asm("mma.sync.aligned.m16n8k16.row.col.f32.bf16.bf16.f32 "
        "{%0,%1,%2,%3}, {%4,%5,%6,%7}, {%8,%9}, {%0,%1,%2,%3};"
        : "+f"(d[0]), "+f"(d[1]), "+f"(d[2]), "+f"(d[3])
        : "r"(a[0]), "r"(a[1]), "r"(a[2]), "r"(a[3]), "r"(b0), "r"(b1));
}
__device__ __forceinline__ uint32_t b2u(__nv_bfloat162 v) {
    return *reinterpret_cast<uint32_t*>(&v);
}
__device__ __forceinline__ void split_pair(float x, float y,
                                           uint32_t& hi, uint32_t& lo) {
    __nv_bfloat162 h = __float22bfloat162_rn(make_float2(x, y));
    float2 hf = __bfloat1622float2(h);
    __nv_bfloat162 l = __float22bfloat162_rn(make_float2(x - hf.x, y - hf.y));
    hi = b2u(h); lo = b2u(l);
}

// ---------------------------------------------------------------------------
// Conversion kernels
// ---------------------------------------------------------------------------
__global__ void split_kernel(const float* __restrict__ in,
                             __nv_bfloat16* __restrict__ hi,
                             __nv_bfloat16* __restrict__ lo, int n)
{
    int i = (blockIdx.x * blockDim.x + threadIdx.x) * 8;
    if (i >= n) return;
    float4 a = *(const float4*)(in + i);
    float4 b = *(const float4*)(in + i + 4);
    float v[8] = {a.x, a.y, a.z, a.w, b.x, b.y, b.z, b.w};
    __nv_bfloat16 h[8], l[8];
#pragma unroll
    for (int j = 0; j < 8; j++) {
        h[j] = __float2bfloat16(v[j]);
        l[j] = __float2bfloat16(v[j] - __bfloat162float(h[j]));
    }
    *(uint4*)(hi + i) = *(uint4*)h;
    *(uint4*)(lo + i) = *(uint4*)l;
}

// W [K][N] row-major -> Wt hi/lo [N][K]
__global__ void transpose_split(const float* __restrict__ W,
                                __nv_bfloat16* __restrict__ Thi,
                                __nv_bfloat16* __restrict__ Tlo,
                                int K, int N)
{
    __shared__ float tile[32][33];
    int k0 = blockIdx.y * 32, n0 = blockIdx.x * 32;
    int tx = threadIdx.x, ty = threadIdx.y;
#pragma unroll
    for (int i = ty; i < 32; i += 8)
        tile[i][tx] = W[(size_t)(k0 + i) * N + n0 + tx];
    __syncthreads();
#pragma unroll
    for (int i = ty; i < 32; i += 8) {
        float v = tile[tx][i];
        __nv_bfloat16 h = __float2bfloat16(v);
        float r = v - __bfloat162float(h);
        Thi[(size_t)(n0 + i) * K + k0 + tx] = h;
        Tlo[(size_t)(n0 + i) * K + k0 + tx] = __float2bfloat16(r);
    }
}

// ---------------------------------------------------------------------------
// mma.sync bf16 split GEMM. Per-nj load-then-use B fragments (interleaves
// LDSM with HMMA, cuts live operand registers). Per-accumulator order
// HH->HL->LH preserved (bit-identical results).
// ---------------------------------------------------------------------------
#define PAD 40
#define MAT_EL (128 * PAD)
#define MAT_B (MAT_EL * 2)
#define STAGE_B (4 * MAT_B)
#define GEMM_SMEM (2 * STAGE_B)
#define NCHUNK (GK / 32)

__global__ __launch_bounds__(256) void tc_gemm_mma(
    const __nv_bfloat16* __restrict__ Ah, const __nv_bfloat16* __restrict__ Al,
    const __nv_bfloat16* __restrict__ Bh, const __nv_bfloat16* __restrict__ Bl,
    const float* __restrict__ bias, float* __restrict__ Co,
    __nv_bfloat16* __restrict__ Chi, __nv_bfloat16* __restrict__ Clo,
    int N, int split_out)
{
    extern __shared__ char smem[];
    const uint32_t sb = smem_u32(smem);
    const int tid = threadIdx.x;
    const int wid = tid >> 5, lane = tid & 31;
    const int warp_m = wid >> 1, warp_n = wid & 1;
    const int m0 = blockIdx.y * 128, n0 = blockIdx.x * 128;

    const __nv_bfloat16* srcs[4] = {
        Ah + (size_t)m0 * GK, Al + (size_t)m0 * GK,
        Bh + (size_t)n0 * GK, Bl + (size_t)n0 * GK };

    auto prefetch = [&](int c, int stage) {
        const int k0 = c * 32;
        const uint32_t so = sb + stage * STAGE_B;
#pragma unroll
        for (int msel = 0; msel < 4; msel++) {
#pragma unroll
            for (int i = 0; i < 2; i++) {
                int idx = tid + i * 256;
                int r = idx >> 2, seg = idx & 3;
                uint32_t dst = so + msel * MAT_B + (uint32_t)(r * PAD + seg * 8) * 2;
                cp_async16(dst, srcs[msel] + (size_t)r * GK + k0 + seg * 8);
            }
        }
    };

    float acc[2][8][4];
#pragma unroll
    for (int a = 0; a < 2; a++)
#pragma unroll
        for (int b = 0; b < 8; b++)
#pragma unroll
            for (int c = 0; c < 4; c++) acc[a][b][c] = 0.f;

    prefetch(0, 0);
    cp_commit();

    const int a_row = (lane & 15);
    const int a_col8 = (lane >> 4) << 3;
    const int b_tile = lane >> 3;
    const int b_rin = lane & 7;
    const int b_nrow = ((b_tile >> 1) << 3) + b_rin;
    const int b_kcol = (b_tile & 1) << 3;

    for (int c = 0; c < NCHUNK; c++) {
        const int stage = c & 1;
        if (c + 1 < NCHUNK) { prefetch(c + 1, stage ^ 1); cp_commit(); }
        if (c + 1 < NCHUNK) cp_wait<1>(); else cp_wait<0>();
        __syncthreads();

        const uint32_t so = sb + stage * STAGE_B;
#pragma unroll
        for (int ks = 0; ks < 2; ks++) {
            uint32_t aH[2][4], aL[2][4];
#pragma unroll
            for (int mi = 0; mi < 2; mi++) {
                uint32_t off = (uint32_t)((warp_m * 32 + mi * 16 + a_row) * PAD
                                          + ks * 16 + a_col8) * 2;
                ldm_x4(aH[mi], so + 0 * MAT_B + off);
                ldm_x4(aL[mi], so + 1 * MAT_B + off);
            }
            // per-nj load-then-use: 2 ldmatrix then 12 MMAs, LDSM/HMMA overlap
#pragma unroll
            for (int nj = 0; nj < 4; nj++) {
                uint32_t bH[4], bL[4];
                uint32_t off = (uint32_t)((warp_n * 64 + nj * 16 + b_nrow) * PAD
                                          + ks * 16 + b_kcol) * 2;
                ldm_x4(bH, so + 2 * MAT_B + off);
                ldm_x4(bL, so + 3 * MAT_B + off);
#pragma unroll
                for (int mi = 0; mi < 2; mi++) {
                    mma_bf16_v(acc[mi][nj * 2],     aH[mi], bH[0], bH[1]);
                    mma_bf16_v(acc[mi][nj * 2 + 1], aH[mi], bH[2], bH[3]);
                    mma_bf16_v(acc[mi][nj * 2],     aH[mi], bL[0], bL[1]);
                    mma_bf16_v(acc[mi][nj * 2 + 1], aH[mi], bL[2], bL[3]);
                    mma_bf16_v(acc[mi][nj * 2],     aL[mi], bH[0], bH[1]);
                    mma_bf16_v(acc[mi][nj * 2 + 1], aL[mi], bH[2], bH[3]);
                }
            }
        }
        __syncthreads();
    }

    const int r_base = m0 + warp_m * 32 + (lane >> 2);
    const int c_base = n0 + warp_n * 64 + (lane & 3) * 2;
    if (split_out) {
#pragma unroll
        for (int mi = 0; mi < 2; mi++) {
#pragma unroll
            for (int nj8 = 0; nj8 < 8; nj8++) {
                int col = c_base + nj8 * 8;
                float b0 = __ldg(bias + col), b1 = __ldg(bias + col + 1);
                int r0 = r_base + mi * 16;
                uint32_t hh, ll;
                split_pair(acc[mi][nj8][0] + b0, acc[mi][nj8][1] + b1, hh, ll);
                *(uint32_t*)(Chi + (size_t)r0 * N + col) = hh;
                *(uint32_t*)(Clo + (size_t)r0 * N + col) = ll;
                split_pair(acc[mi][nj8][2] + b0, acc[mi][nj8][3] + b1, hh, ll);
                *(uint32_t*)(Chi + (size_t)(r0 + 8) * N + col) = hh;
                *(uint32_t*)(Clo + (size_t)(r0 + 8) * N + col) = ll;
            }
        }
    } else {
#pragma unroll
        for (int mi = 0; mi < 2; mi++) {
#pragma unroll
            for (int nj8 = 0; nj8 < 8; nj8++) {
                int col = c_base + nj8 * 8;
                float b0 = __ldg(bias + col), b1 = __ldg(bias + col + 1);
                int r0 = r_base + mi * 16;
                Co[(size_t)r0 * N + col]           = acc[mi][nj8][0] + b0;
                Co[(size_t)r0 * N + col + 1]       = acc[mi][nj8][1] + b1;
                Co[(size_t)(r0 + 8) * N + col]     = acc[mi][nj8][2] + b0;
                Co[(size_t)(r0 + 8) * N + col + 1] = acc[mi][nj8][3] + b1;
            }
        }
    }
}

// ---------------------------------------------------------------------------
// Tensor-core causal flash attention (unchanged from round 9).
// ---------------------------------------------------------------------------
#define PADA 72
#define KTB  9216
#define QB   18432
#define KVS  36864
#define KVBASE (2 * QB)
#define FLASH_SMEM (KVBASE + 2 * KVS)   // 110592

__global__ __launch_bounds__(256) void flash_mma_kernel(
    const __nv_bfloat16* __restrict__ qkvh,
    const __nv_bfloat16* __restrict__ qkvl,
    __nv_bfloat16* __restrict__ yhi, __nv_bfloat16* __restrict__ ylo)
{
    extern __shared__ __align__(16) char smem[];
    const uint32_t sb = smem_u32(smem);
    const int tid = threadIdx.x;
    const int wid = tid >> 5, lane = tid & 31;
    const int bh = blockIdx.x, b = bh >> 4, h = bh & 15;
    const int qt = (T_ / 128 - 1) - blockIdx.y;  // long CTAs first
    const int q0 = qt * 128;
    const size_t rowbase = (size_t)b * T_ * C3;

    auto fillKV = [&](int kt, int s) {
        const int k0 = kt * 64;
        const uint32_t so = sb + KVBASE + s * KVS;
#pragma unroll
        for (int i = 0; i < 8; i++) {
            int idx = tid + i * 256;
            int mat = idx >> 9;            // 0=Kh 1=Kl 2=Vh 3=Vl
            int rem = idx & 511;
            int r = rem >> 3, seg = rem & 7;
            const __nv_bfloat16* src =
                ((mat & 1) ? qkvl : qkvh) + rowbase + (size_t)(k0 + r) * C3
                + ((mat >> 1) ? 2 * C_ : C_) + h * D_ + seg * 8;
            cp_async16(so + (uint32_t)(mat * KTB + r * 144 + seg * 16), src);
        }
    };

    // ---- stage Q (unscaled hi/lo; 1/8 applied to scores post-MMA) ----
    {
#pragma unroll
        for (int i = 0; i < 8; i++) {
            int idx = tid + i * 256;       // 0..2047
            int mat = idx >> 10;           // 0=hi 1=lo
            int rem = idx & 1023;
            int r = rem >> 3, seg = rem & 7;
            const __nv_bfloat16* src =
                (mat ? qkvl : qkvh) + rowbase + (size_t)(q0 + r) * C3
                + h * D_ + seg * 8;
            cp_async16(sb + (uint32_t)(mat * QB + r * 144 + seg * 16), src);
        }
    }
    cp_commit();
    fillKV(0, 0);
    cp_commit();

    const int a_row = lane & 15;
    const int a_col8 = (lane >> 4) << 3;
    const int b_tile = lane >> 3;
    const int b_nrow = ((b_tile >> 1) << 3) + (lane & 7);
    const int b_kcol = (b_tile & 1) << 3;
    const int v_krow = ((b_tile & 1) << 3) + (lane & 7);
    const int v_ncol = (b_tile >> 1) << 3;

    cp_wait<1>();      // Q group done (KV0 may still be in flight)
    __syncthreads();

    uint32_t aQh[4][4], aQl[4][4];
#pragma unroll
    for (int ks = 0; ks < 4; ks++) {
        uint32_t off = (uint32_t)((wid * 16 + a_row) * PADA + ks * 16 + a_col8) * 2;
        ldm_x4(aQh[ks], sb + off);
        ldm_x4(aQl[ks], sb + QB + off);
    }

    float oacc[8][4];
#pragma unroll
    for (int i = 0; i < 8; i++)
#pragma unroll
        for (int j = 0; j < 4; j++) oacc[i][j] = 0.f;
    float mrow[2] = {-1e30f, -1e30f};
    float lrow[2] = {0.f, 0.f};

    const int ntiles = 2 * (qt + 1);
    for (int kt = 0; kt < ntiles; kt++) {
        const int s = kt & 1;
        const int k0 = kt * 64;
        __syncthreads();   // all warps done reading stage s^1 (tile kt-1)
        if (kt + 1 < ntiles) { fillKV(kt + 1, s ^ 1); cp_commit(); }
        if (kt + 1 < ntiles) cp_wait<1>(); else cp_wait<0>();
        __syncthreads();   // stage s (tile kt) visible to all

        const uint32_t kvso = sb + KVBASE + s * KVS;

        // ---- S = Q @ K^T (3-pass) ----
        float sacc[8][4];
#pragma unroll
        for (int i = 0; i < 8; i++)
#pragma unroll
            for (int j = 0; j < 4; j++) sacc[i][j] = 0.f;
#pragma unroll
        for (int ks = 0; ks < 4; ks++) {
            uint32_t bH[4], bL[4];
#pragma unroll
            for (int nj = 0; nj < 4; nj++) {
                uint32_t off = (uint32_t)((nj * 16 + b_nrow) * PADA
                                          + ks * 16 + b_kcol) * 2;
                ldm_x4(bH, kvso + off);
                ldm_x4(bL, kvso + KTB + off);
                mma_bf16(sacc[nj * 2],     aQh[ks], bH[0], bH[1]);
                mma_bf16(sacc[nj * 2 + 1], aQh[ks], bH[2], bH[3]);
                mma_bf16(sacc[nj * 2],     aQh[ks], bL[0], bL[1]);
                mma_bf16(sacc[nj * 2 + 1], aQh[ks], bL[2], bL[3]);
                mma_bf16(sacc[nj * 2],     aQl[ks], bH[0], bH[1]);
                mma_bf16(sacc[nj * 2 + 1], aQl[ks], bH[2], bH[3]);
            }
        }
        // apply 1/sqrt(D) = 1/8 (exact pow2; commutes with the bf16 split)
#pragma unroll
        for (int nb = 0; nb < 8; nb++) {
            sacc[nb][0] *= 0.125f; sacc[nb][1] *= 0.125f;
            sacc[nb][2] *= 0.125f; sacc[nb][3] *= 0.125f;
        }

        // ---- causal mask (last two tiles only) ----
        if (k0 >= q0) {
            const int qg = q0 + wid * 16 + (lane >> 2);
            const int cg = k0 + (lane & 3) * 2;
#pragma unroll
            for (int nb = 0; nb < 8; nb++) {
                int col = cg + nb * 8;
                if (col > qg)          sacc[nb][0] = -1e30f;
                if (col + 1 > qg)      sacc[nb][1] = -1e30f;
                if (col > qg + 8)      sacc[nb][2] = -1e30f;
                if (col + 1 > qg + 8)  sacc[nb][3] = -1e30f;
            }
        }

        // ---- online softmax ----
        float mn0 = mrow[0], mn1 = mrow[1];
#pragma unroll
        for (int nb = 0; nb < 8; nb++) {
            mn0 = fmaxf(mn0, fmaxf(sacc[nb][0], sacc[nb][1]));
            mn1 = fmaxf(mn1, fmaxf(sacc[nb][2], sacc[nb][3]));
        }
        mn0 = fmaxf(mn0, __shfl_xor_sync(0xFFFFFFFF, mn0, 1));
        mn0 = fmaxf(mn0, __shfl_xor_sync(0xFFFFFFFF, mn0, 2));
        mn1 = fmaxf(mn1, __shfl_xor_sync(0xFFFFFFFF, mn1, 1));
        mn1 = fmaxf(mn1, __shfl_xor_sync(0xFFFFFFFF, mn1, 2));
        const float corr0 = __expf(mrow[0] - mn0);
        const float corr1 = __expf(mrow[1] - mn1);
        mrow[0] = mn0; mrow[1] = mn1;

        float ps0 = 0.f, ps1 = 0.f;
#pragma unroll
        for (int nb = 0; nb < 8; nb++) {
            sacc[nb][0] = __expf(sacc[nb][0] - mn0);
            sacc[nb][1] = __expf(sacc[nb][1] - mn0);
            sacc[nb][2] = __expf(sacc[nb][2] - mn1);
            sacc[nb][3] = __expf(sacc[nb][3] - mn1);
            ps0 += sacc[nb][0] + sacc[nb][1];
            ps1 += sacc[nb][2] + sacc[nb][3];
        }
        ps0 += __shfl_xor_sync(0xFFFFFFFF, ps0, 1);
        ps0 += __shfl_xor_sync(0xFFFFFFFF, ps0, 2);
        ps1 += __shfl_xor_sync(0xFFFFFFFF, ps1, 1);
        ps1 += __shfl_xor_sync(0xFFFFFFFF, ps1, 2);
        lrow[0] = lrow[0] * corr0 + ps0;
        lrow[1] = lrow[1] * corr1 + ps1;
#pragma unroll
        for (int nb = 0; nb < 8; nb++) {
            oacc[nb][0] *= corr0; oacc[nb][1] *= corr0;
            oacc[nb][2] *= corr1; oacc[nb][3] *= corr1;
        }

        // ---- O += P @ V (3-pass, V via ldmatrix.trans) ----
#pragma unroll
        for (int ks = 0; ks < 4; ks++) {
            uint32_t pH[4], pL[4];
            split_pair(sacc[2 * ks][0],     sacc[2 * ks][1],     pH[0], pL[0]);
            split_pair(sacc[2 * ks][2],     sacc[2 * ks][3],     pH[1], pL[1]);
            split_pair(sacc[2 * ks + 1][0], sacc[2 * ks + 1][1], pH[2], pL[2]);
            split_pair(sacc[2 * ks + 1][2], sacc[2 * ks + 1][3], pH[3], pL[3]);
#pragma unroll
            for (int nj = 0; nj < 4; nj++) {
                uint32_t bH[4], bL[4];
                uint32_t off = (uint32_t)((ks * 16 + v_krow) * PADA
                                          + nj * 16 + v_ncol) * 2;
                ldm_x4_trans(bH, kvso + 2 * KTB + off);
                ldm_x4_trans(bL, kvso + 3 * KTB + off);
                mma_bf16(oacc[nj * 2],     pH, bH[0], bH[1]);
                mma_bf16(oacc[nj * 2 + 1], pH, bH[2], bH[3]);
                mma_bf16(oacc[nj * 2],     pH, bL[0], bL[1]);
                mma_bf16(oacc[nj * 2 + 1], pH, bL[2], bL[3]);
                mma_bf16(oacc[nj * 2],     pL, bH[0], bH[1]);
                mma_bf16(oacc[nj * 2 + 1], pL, bH[2], bH[3]);
            }
        }
    }

    // ---- normalize and write y as bf16 hi/lo (fused split) ----
    const float inv0 = 1.f / lrow[0];
    const float inv1 = 1.f / lrow[1];
    const int rg = q0 + wid * 16 + (lane >> 2);
    const size_t e0 = ((size_t)b * T_ + rg) * C_ + h * D_ + (lane & 3) * 2;
#pragma unroll
    for (int nb = 0; nb < 8; nb++) {
        uint32_t h0, l0, h1, l1;
        split_pair(oacc[nb][0] * inv0, oacc[nb][1] * inv0, h0, l0);
        split_pair(oacc[nb][2] * inv1, oacc[nb][3] * inv1, h1, l1);
        *(uint32_t*)(yhi + e0 + nb * 8)          = h0;
        *(uint32_t*)(ylo + e0 + nb * 8)          = l0;
        *(uint32_t*)(yhi + e0 + 8 * C_ + nb * 8) = h1;
        *(uint32_t*)(ylo + e0 + 8 * C_ + nb * 8) = l1;
    }
}

// ---------------------------------------------------------------------------
extern "C" void kernel_launch(void* const* d_in, const int* in_sizes, int n_in,
                              void* d_out, int out_size)
{
    const float* x      = (const float*)d_in[0];
    const float* W_attn = (const float*)d_in[1];
    const float* b_attn = (const float*)d_in[2];
    const float* W_proj = (const float*)d_in[3];
    const float* b_proj = (const float*)d_in[4];
    float* out = (float*)d_out;

    __nv_bfloat16 *qkvh, *qkvl, *xhi, *xlo, *yhi, *ylo, *wahi, *walo, *wphi, *wplo;
    cudaGetSymbolAddress((void**)&qkvh, g_qkvh);
    cudaGetSymbolAddress((void**)&qkvl, g_qkvl);
    cudaGetSymbolAddress((void**)&xhi, g_xhi);
    cudaGetSymbolAddress((void**)&xlo, g_xlo);
    cudaGetSymbolAddress((void**)&yhi, g_yhi);
    cudaGetSymbolAddress((void**)&ylo, g_ylo);
    cudaGetSymbolAddress((void**)&wahi, g_wahi);
    cudaGetSymbolAddress((void**)&walo, g_walo);
    cudaGetSymbolAddress((void**)&wphi, g_wphi);
    cudaGetSymbolAddress((void**)&wplo, g_wplo);

    cudaFuncSetAttribute(tc_gemm_mma, cudaFuncAttributeMaxDynamicSharedMemorySize,
                         GEMM_SMEM);
    cudaFuncSetAttribute(flash_mma_kernel,
                         cudaFuncAttributeMaxDynamicSharedMemorySize, FLASH_SMEM);

    const int NTOK_EL = M_TOK * C_;

    // 1) split x -> bf16 hi/lo
    split_kernel<<<NTOK_EL / 8 / 256, 256>>>(x, xhi, xlo, NTOK_EL);
    // 2) transpose+split weights
    transpose_split<<<dim3(C3 / 32, C_ / 32), dim3(32, 8)>>>(W_attn, wahi, walo, C_, C3);
    transpose_split<<<dim3(C_ / 32, C_ / 32), dim3(32, 8)>>>(W_proj, wphi, wplo, C_, C_);
    // 3) QKV GEMM -> qkv bf16 hi/lo (split fused in epilogue)
    tc_gemm_mma<<<dim3(C3 / 128, M_TOK / 128), 256, GEMM_SMEM>>>(
        xhi, xlo, wahi, walo, b_attn, nullptr, qkvh, qkvl, C3, 1);
    // 4) causal flash attention (cp.async staging, double-buffered KV)
    flash_mma_kernel<<<dim3(B_ * H_, T_ / 128), 256, FLASH_SMEM>>>(
        qkvh, qkvl, yhi, ylo);
    // 5) proj GEMM -> d_out (fp32)
    tc_gemm_mma<<<dim3(C_ / 128, M_TOK / 128), 256, GEMM_SMEM>>>(
        yhi, ylo, wphi, wplo, b_proj, out, nullptr, nullptr, C_, 0);
}